// round 10
// baseline (speedup 1.0000x reference)
#include <cuda_runtime.h>
#include <cuda_bf16.h>
#include <cuda_fp16.h>
#include <cstdint>
#include <math.h>

#define BB 8
#define LQ 512
#define LK 2048
#define NH 16
#define HID 1024
#define NT (LK/64)

using bf16  = __nv_bfloat16;
using bf162 = __nv_bfloat162;

#define LOG2E 1.4426950408889634f

// ---------------- scratch ----------------
__device__ unsigned char g_q8[BB*LQ*HID];   // e4m3, scaled 0.125*log2e*16
__device__ unsigned char g_k8[BB*LK*HID];   // e4m3, scaled 8
__device__ __half g_v  [BB*LK*HID];
__device__ __half g_ctx[BB*LQ*HID];
__device__ __half g_wl [HID*HID];
__device__ float  g_lin[BB*LQ*HID];

// ---------------- helpers ----------------
__device__ __forceinline__ unsigned sptr(const void* p){
    return (unsigned)__cvta_generic_to_shared(p);
}
__device__ __forceinline__ void ldsm4(unsigned a, unsigned& r0, unsigned& r1, unsigned& r2, unsigned& r3){
    asm volatile("ldmatrix.sync.aligned.m8n8.x4.shared.b16 {%0,%1,%2,%3},[%4];"
                 : "=r"(r0),"=r"(r1),"=r"(r2),"=r"(r3) : "r"(a));
}
__device__ __forceinline__ void ldsm4t(unsigned a, unsigned& r0, unsigned& r1, unsigned& r2, unsigned& r3){
    asm volatile("ldmatrix.sync.aligned.m8n8.x4.trans.shared.b16 {%0,%1,%2,%3},[%4];"
                 : "=r"(r0),"=r"(r1),"=r"(r2),"=r"(r3) : "r"(a));
}
__device__ __forceinline__ void mma_bf16(float* c, const unsigned* a, unsigned b0, unsigned b1){
    asm volatile("mma.sync.aligned.m16n8k16.row.col.f32.bf16.bf16.f32 "
                 "{%0,%1,%2,%3},{%4,%5,%6,%7},{%8,%9},{%0,%1,%2,%3};"
                 : "+f"(c[0]),"+f"(c[1]),"+f"(c[2]),"+f"(c[3])
                 : "r"(a[0]),"r"(a[1]),"r"(a[2]),"r"(a[3]),"r"(b0),"r"(b1));
}
__device__ __forceinline__ void mma_f16c(unsigned* d, const unsigned* a, unsigned b0, unsigned b1){
    asm volatile("mma.sync.aligned.m16n8k16.row.col.f16.f16.f16.f16 "
                 "{%0,%1},{%2,%3,%4,%5},{%6,%7},{%0,%1};"
                 : "+r"(d[0]),"+r"(d[1])
                 : "r"(a[0]),"r"(a[1]),"r"(a[2]),"r"(a[3]),"r"(b0),"r"(b1));
}
// fp8 e4m3 mma, k=32, f32 accum (sm_89-family feature, plain target)
__device__ __forceinline__ void mma_fp8(float* c, const unsigned* a, unsigned b0, unsigned b1){
    asm volatile("mma.sync.aligned.m16n8k32.row.col.f32.e4m3.e4m3.f32 "
                 "{%0,%1,%2,%3},{%4,%5,%6,%7},{%8,%9},{%0,%1,%2,%3};"
                 : "+f"(c[0]),"+f"(c[1]),"+f"(c[2]),"+f"(c[3])
                 : "r"(a[0]),"r"(a[1]),"r"(a[2]),"r"(a[3]),"r"(b0),"r"(b1));
}
__device__ __forceinline__ unsigned short cvt_e4m3x2(float hi, float lo){
    unsigned short u;
    asm("cvt.rn.satfinite.e4m3x2.f32 %0, %1, %2;" : "=h"(u) : "f"(hi), "f"(lo));
    return u;
}
__device__ __forceinline__ unsigned cvt_f16x2(float hi, float lo){
    unsigned u;
    asm("cvt.rn.f16x2.f32 %0, %1, %2;" : "=r"(u) : "f"(hi), "f"(lo));
    return u;
}
__device__ __forceinline__ void cp16(void* dst, const void* src){
    asm volatile("cp.async.cg.shared.global [%0],[%1],16;" :: "r"(sptr(dst)),"l"(src));
}
__device__ __forceinline__ void cp_commit(){ asm volatile("cp.async.commit_group;"); }
__device__ __forceinline__ void cp_wait1(){ asm volatile("cp.async.wait_group 1;"); }
__device__ __forceinline__ void st_sw4(bf16* s, int row, int c4, float4 f){
    bf162 lo = __floats2bfloat162_rn(f.x, f.y);
    bf162 hi = __floats2bfloat162_rn(f.z, f.w);
    int chunk = c4 >> 1, half = c4 & 1;
    uint2 v = make_uint2(*reinterpret_cast<unsigned*>(&lo), *reinterpret_cast<unsigned*>(&hi));
    *reinterpret_cast<uint2*>(s + row*64 + ((chunk ^ (row & 7)) << 3) + half*4) = v;
}

// ---------------- W_lin fp32 -> f16 prepass ----------------
__global__ __launch_bounds__(256) void wconv_kernel(const float* __restrict__ W){
    int i = (blockIdx.x*256 + threadIdx.x)*4;
    float4 v = *(const float4*)(W + i);
    __half2 lo = __floats2half2_rn(v.x, v.y);
    __half2 hi = __floats2half2_rn(v.z, v.w);
    *(uint2*)(g_wl + i) = make_uint2(*reinterpret_cast<unsigned*>(&lo), *reinterpret_cast<unsigned*>(&hi));
}

// ---------------- Q projection -> e4m3 (scaled 0.125*log2e*16) ------------------
__global__ __launch_bounds__(256) void qproj_kernel(const float* __restrict__ x,
                                                    const float* __restrict__ Wq){
    __shared__ bf16 sX[128*64];
    __shared__ bf16 sW[64*64];
    const int t = threadIdx.x, lane = t & 31, w = t >> 5;
    const int rbase = blockIdx.x * 128;
#pragma unroll
    for (int it = 0; it < 8; it++){
        int idx = it*256 + t, row = idx >> 4, c4 = idx & 15;
        st_sw4(sX, row, c4, *(const float4*)(x + (size_t)(rbase+row)*64 + c4*4));
    }
#pragma unroll
    for (int it = 0; it < 4; it++){
        int idx = it*256 + t, row = idx >> 4, c4 = idx & 15;
        st_sw4(sW, row, c4, *(const float4*)(Wq + row*64 + c4*4));
    }
    __syncthreads();
    float acc[8][4] = {};
    const int rA  = w*16 + (lane & 7) + (lane & 8);
    const int rB0 = (lane & 7) + ((lane & 16) >> 1);
#pragma unroll
    for (int kk = 0; kk < 4; kk++){
        unsigned af[4];
        int cA = 2*kk + (lane >> 4);
        ldsm4(sptr(sX + rA*64 + ((cA ^ (rA & 7)) << 3)), af[0], af[1], af[2], af[3]);
        int cB = 2*kk + ((lane >> 3) & 1);
#pragma unroll
        for (int jp = 0; jp < 4; jp++){
            int r = jp*16 + rB0;
            unsigned b0, b1, b2, b3;
            ldsm4(sptr(sW + r*64 + ((cB ^ (r & 7)) << 3)), b0, b1, b2, b3);
            mma_bf16(acc[2*jp],   af, b0, b1);
            mma_bf16(acc[2*jp+1], af, b2, b3);
        }
    }
    const float qs = 0.125f * LOG2E * 16.0f;
    const int g = lane >> 2, cc = (lane & 3)*2;
#pragma unroll
    for (int j = 0; j < 8; j++){
        size_t r0 = (size_t)(rbase + w*16 + g)*64 + j*8 + cc;
        *(unsigned short*)(g_q8 + r0)       = cvt_e4m3x2(acc[j][1]*qs, acc[j][0]*qs);
        *(unsigned short*)(g_q8 + r0 + 512) = cvt_e4m3x2(acc[j][3]*qs, acc[j][2]*qs);
    }
}

// ---------------- K/V projection: K -> e4m3 (x8), V -> f16 ----------------------
__global__ __launch_bounds__(256) void kvproj_kernel(const float* __restrict__ x,
                                                     const float* __restrict__ Wk,
                                                     const float* __restrict__ Wv){
    __shared__ bf16 sX [128*64];
    __shared__ bf16 sWk[64*64];
    __shared__ bf16 sWv[64*64];
    const int t = threadIdx.x, lane = t & 31, w = t >> 5;
    const int rbase = blockIdx.x * 128;
#pragma unroll
    for (int it = 0; it < 8; it++){
        int idx = it*256 + t, row = idx >> 4, c4 = idx & 15;
        st_sw4(sX, row, c4, *(const float4*)(x + (size_t)(rbase+row)*64 + c4*4));
    }
#pragma unroll
    for (int it = 0; it < 4; it++){
        int idx = it*256 + t, row = idx >> 4, c4 = idx & 15;
        st_sw4(sWk, row, c4, *(const float4*)(Wk + row*64 + c4*4));
        st_sw4(sWv, row, c4, *(const float4*)(Wv + row*64 + c4*4));
    }
    __syncthreads();
    float ak[8][4] = {}, av[8][4] = {};
    const int rA  = w*16 + (lane & 7) + (lane & 8);
    const int rB0 = (lane & 7) + ((lane & 16) >> 1);
#pragma unroll
    for (int kk = 0; kk < 4; kk++){
        unsigned af[4];
        int cA = 2*kk + (lane >> 4);
        ldsm4(sptr(sX + rA*64 + ((cA ^ (rA & 7)) << 3)), af[0], af[1], af[2], af[3]);
        int cB = 2*kk + ((lane >> 3) & 1);
#pragma unroll
        for (int jp = 0; jp < 4; jp++){
            int r = jp*16 + rB0;
            unsigned b0, b1, b2, b3;
            ldsm4(sptr(sWk + r*64 + ((cB ^ (r & 7)) << 3)), b0, b1, b2, b3);
            mma_bf16(ak[2*jp],   af, b0, b1);
            mma_bf16(ak[2*jp+1], af, b2, b3);
            ldsm4(sptr(sWv + r*64 + ((cB ^ (r & 7)) << 3)), b0, b1, b2, b3);
            mma_bf16(av[2*jp],   af, b0, b1);
            mma_bf16(av[2*jp+1], af, b2, b3);
        }
    }
    const int g = lane >> 2, cc = (lane & 3)*2;
#pragma unroll
    for (int j = 0; j < 8; j++){
        size_t r0 = (size_t)(rbase + w*16 + g)*64 + j*8 + cc;
        *(unsigned short*)(g_k8 + r0)       = cvt_e4m3x2(ak[j][1]*8.f, ak[j][0]*8.f);
        *(unsigned short*)(g_k8 + r0 + 512) = cvt_e4m3x2(ak[j][3]*8.f, ak[j][2]*8.f);
        *(__half2*)(g_v + r0)       = __floats2half2_rn(av[j][0], av[j][1]);
        *(__half2*)(g_v + r0 + 512) = __floats2half2_rn(av[j][2], av[j][3]);
    }
}

// ---------------- flash attention: fp8 QK (k32), f16 PV -------------------------
// Q/K fp8 smem: 2 rows per 128B (row r -> (r>>1)*128 + (r&1)*64), 16B-chunk swizzle.
__global__ __launch_bounds__(128) void attn_kernel(const float* __restrict__ kg_mask){
    extern __shared__ char sm[];
    unsigned char* sQ = (unsigned char*)sm;            // 8KB  (128 q-rows x 64B)
    unsigned char* sK = (unsigned char*)(sm + 8192);   // 2 x 4KB
    __half* sV  = (__half*)(sm + 16384);               // 2 x 8KB
    __half* skb = (__half*)(sm + 32768);               // 4KB

    const int t = threadIdx.x, lane = t & 31, w = t >> 5;
    const int qt = blockIdx.x, h = blockIdx.y, b = blockIdx.z;

    auto issue = [&](int kt){
        unsigned char* dk = sK + (kt & 1)*4096;
        __half* dv = sV + (kt & 1)*4096;
        const unsigned char* gk = g_k8 + (size_t)(b*LK + kt*64)*HID + h*64;
        const __half*        gv = g_v  + (size_t)(b*LK + kt*64)*HID + h*64;
#pragma unroll
        for (int it = 0; it < 2; it++){               // K: 256 x 16B
            int idx = it*128 + t, key = idx >> 2, c2 = idx & 3;
            unsigned so = (key >> 1)*128 + (key & 1)*64 + ((c2 ^ ((key >> 1) & 3)) << 4);
            cp16(dk + so, gk + (size_t)key*HID + c2*16);
        }
#pragma unroll
        for (int it = 0; it < 4; it++){               // V: 512 x 16B (f16, SW rows)
            int idx = it*128 + t, rr = idx >> 3, c = idx & 7;
            unsigned so = rr*64 + ((c ^ (rr & 7)) << 3);
            cp16(dv + so, gv + (size_t)rr*HID + c*8);
        }
        cp_commit();
    };

    issue(0); issue(1);

    for (int i = t; i < LK; i += 128)
        skb[i] = __float2half((1.0f - kg_mask[b*LK + i]) * (-30000.f));

    // Q tile fp8
#pragma unroll
    for (int it = 0; it < 4; it++){
        int idx = it*128 + t, row = idx >> 2, c2 = idx & 3;
        unsigned so = (row >> 1)*128 + (row & 1)*64 + ((c2 ^ ((row >> 1) & 3)) << 4);
        *(uint4*)(sQ + so) = *(const uint4*)(g_q8 + (size_t)(b*LQ + qt*128 + row)*HID + h*64 + c2*16);
    }
    __syncthreads();

    // Q fragments: 2 rowgroups x 2 k32-chunks
    unsigned qf[2][2][4];
#pragma unroll
    for (int rg = 0; rg < 2; rg++){
        int rA = w*32 + rg*16 + (lane & 7) + (lane & 8);
#pragma unroll
        for (int kk = 0; kk < 2; kk++){
            int cA = 2*kk + (lane >> 4);
            unsigned a = sptr(sQ) + (rA >> 1)*128 + (rA & 1)*64 + ((cA ^ ((rA >> 1) & 3)) << 4);
            ldsm4(a, qf[rg][kk][0], qf[rg][kk][1], qf[rg][kk][2], qf[rg][kk][3]);
        }
    }

    unsigned O2[2][8][2] = {};
    unsigned lacc[2][2] = {};
    const unsigned ONESH = 0x3C003C00u;
    const __half2 DSC2 = __floats2half2_rn(0.0078125f, 0.0078125f);   // 2^-7 descale
    const int rB0 = (lane & 7) + ((lane & 16) >> 1);
    const int rV0 = (lane & 7) + (lane & 8);

    for (int kt = 0; kt < NT; kt++){
        cp_wait1();
        __syncthreads();
        unsigned char* K = sK + (kt & 1)*4096;
        __half*        V = sV + (kt & 1)*4096;

#pragma unroll
        for (int hk = 0; hk < 2; hk++){
            // ---- S = Q K^T (fp8 k32, f32 accum), 32 keys ----
            float S[2][4][4] = {};
#pragma unroll
            for (int kk = 0; kk < 2; kk++){
                int cB = 2*kk + ((lane >> 3) & 1);
#pragma unroll
                for (int jp = 0; jp < 2; jp++){
                    int rB = hk*32 + jp*16 + rB0;
                    unsigned ab = sptr(K) + (rB >> 1)*128 + (rB & 1)*64 + ((cB ^ ((rB >> 1) & 3)) << 4);
                    unsigned b0, b1, b2, b3;
                    ldsm4(ab, b0, b1, b2, b3);
                    mma_fp8(S[0][2*jp],   qf[0][kk], b0, b1);
                    mma_fp8(S[0][2*jp+1], qf[0][kk], b2, b3);
                    mma_fp8(S[1][2*jp],   qf[1][kk], b0, b1);
                    mma_fp8(S[1][2*jp+1], qf[1][kk], b2, b3);
                }
            }

            // ---- p = 2^(S/128 + bias) in f16x2 ----
            unsigned pf[2][2][4];
#pragma unroll
            for (int rg = 0; rg < 2; rg++){
#pragma unroll
                for (int j = 0; j < 4; j++){
                    __half2 bias = *(const __half2*)&skb[kt*64 + hk*32 + j*8 + 2*(lane & 3)];
                    unsigned u0 = cvt_f16x2(S[rg][j][1], S[rg][j][0]);
                    unsigned u1 = cvt_f16x2(S[rg][j][3], S[rg][j][2]);
                    __half2 p0 = h2exp2(__hfma2(*(__half2*)&u0, DSC2, bias));
                    __half2 p1 = h2exp2(__hfma2(*(__half2*)&u1, DSC2, bias));
                    pf[rg][j >> 1][(j & 1)*2 + 0] = *reinterpret_cast<unsigned*>(&p0);
                    pf[rg][j >> 1][(j & 1)*2 + 1] = *reinterpret_cast<unsigned*>(&p1);
                }
            }

            // ---- O += P V ; l += P @ ones (f16 MMA) ----
#pragma unroll
            for (int kk2 = 0; kk2 < 2; kk2++){
                int r = hk*32 + kk2*16 + rV0;
                mma_f16c(lacc[0], pf[0][kk2], ONESH, ONESH);
                mma_f16c(lacc[1], pf[1][kk2], ONESH, ONESH);
#pragma unroll
                for (int jp = 0; jp < 4; jp++){
                    int c = 2*jp + (lane >> 4);
                    unsigned v0, v1, v2, v3;
                    ldsm4t(sptr(V + r*64 + ((c ^ (r & 7)) << 3)), v0, v1, v2, v3);
                    mma_f16c(O2[0][2*jp],   pf[0][kk2], v0, v1);
                    mma_f16c(O2[0][2*jp+1], pf[0][kk2], v2, v3);
                    mma_f16c(O2[1][2*jp],   pf[1][kk2], v0, v1);
                    mma_f16c(O2[1][2*jp+1], pf[1][kk2], v2, v3);
                }
            }
        }

        __syncthreads();
        if (kt + 2 < NT) issue(kt + 2);
        else cp_commit();
    }

    // epilogue
    const int g = lane >> 2, cc = (lane & 3)*2;
#pragma unroll
    for (int rg = 0; rg < 2; rg++){
        float l0 = __low2float(*(__half2*)&lacc[rg][0]);
        float l1 = __low2float(*(__half2*)&lacc[rg][1]);
        float inv0 = 1.0f / l0, inv1 = 1.0f / l1;
#pragma unroll
        for (int j = 0; j < 8; j++){
            float2 a = __half22float2(*(__half2*)&O2[rg][j][0]);
            float2 c = __half22float2(*(__half2*)&O2[rg][j][1]);
            size_t r0 = (size_t)(b*LQ + qt*128 + w*32 + rg*16 + g)*HID + h*64 + j*8 + cc;
            *(__half2*)(g_ctx + r0)         = __floats2half2_rn(a.x*inv0, a.y*inv0);
            *(__half2*)(g_ctx + r0 + 8*HID) = __floats2half2_rn(c.x*inv1, c.y*inv1);
        }
    }
}

// ---------------- output linear: f16 MMA, f16 accum, double buffer --------------
__global__ __launch_bounds__(256) void lin_kernel(const float* __restrict__ bias){
    extern __shared__ char sm[];
    __half* sA = (__half*)sm;
    __half* sW = (__half*)(sm + 32768);
    const int t = threadIdx.x, lane = t & 31, w = t >> 5;
    const int ct = blockIdx.x, rt = blockIdx.y;
    const int wrow = (w >> 1)*32, wcol = (w & 1)*64;

    auto issue = [&](int ki, int buf){
        __half* da = sA + buf*8192;
        __half* dw = sW + buf*8192;
#pragma unroll
        for (int it = 0; it < 4; it++){
            int idx = it*256 + t, row = idx >> 3, c = idx & 7;
            unsigned so = row*64 + ((c ^ (row & 7)) << 3);
            cp16(da + so, g_ctx + (size_t)(rt*128 + row)*HID + ki*64 + c*8);
            cp16(dw + so, g_wl  + (size_t)(ct*128 + row)*HID + ki*64 + c*8);
        }
        cp_commit();
    };

    issue(0, 0);
    issue(1, 1);

    unsigned acc2[2][8][2] = {};
    const int rB0 = (lane & 7) + ((lane & 16) >> 1);

    for (int ki = 0; ki < HID/64; ki++){
        cp_wait1();
        __syncthreads();
        __half* A  = sA + (ki & 1)*8192;
        __half* Wt = sW + (ki & 1)*8192;
#pragma unroll
        for (int kk = 0; kk < 4; kk++){
            unsigned af0[4], af1[4];
            int cA = 2*kk + (lane >> 4);
            int rA0 = wrow + (lane & 7) + (lane & 8);
            int rA1 = rA0 + 16;
            ldsm4(sptr(A + rA0*64 + ((cA ^ (rA0 & 7)) << 3)), af0[0], af0[1], af0[2], af0[3]);
            ldsm4(sptr(A + rA1*64 + ((cA ^ (rA1 & 7)) << 3)), af1[0], af1[1], af1[2], af1[3]);
            int cB = 2*kk + ((lane >> 3) & 1);
#pragma unroll
            for (int jp = 0; jp < 4; jp++){
                int r = wcol + jp*16 + rB0;
                unsigned b0, b1, b2, b3;
                ldsm4(sptr(Wt + r*64 + ((cB ^ (r & 7)) << 3)), b0, b1, b2, b3);
                mma_f16c(acc2[0][2*jp],   af0, b0, b1);
                mma_f16c(acc2[0][2*jp+1], af0, b2, b3);
                mma_f16c(acc2[1][2*jp],   af1, b0, b1);
                mma_f16c(acc2[1][2*jp+1], af1, b2, b3);
            }
        }
        __syncthreads();
        if (ki + 2 < HID/64) issue(ki + 2, ki & 1);
        else cp_commit();
    }

    const int g = lane >> 2, cc = (lane & 3)*2;
#pragma unroll
    for (int rg = 0; rg < 2; rg++){
#pragma unroll
        for (int j = 0; j < 8; j++){
            int col = ct*128 + wcol + j*8 + cc;
            float2 bv = *(const float2*)(bias + col);
            float2 a = __half22float2(*(__half2*)&acc2[rg][j][0]);
            float2 c = __half22float2(*(__half2*)&acc2[rg][j][1]);
            size_t r0 = (size_t)(rt*128 + wrow + rg*16 + g)*HID + col;
            *(float2*)(g_lin + r0)         = make_float2(a.x + bv.x, a.y + bv.y);
            *(float2*)(g_lin + r0 + 8*HID) = make_float2(c.x + bv.x, c.y + bv.y);
        }
    }
}

// ---------------- gelu + residual + layernorm ----------------------------------
__global__ __launch_bounds__(256) void final_kernel(const float* __restrict__ resid,
                                                    const float* __restrict__ gamma,
                                                    const float* __restrict__ beta,
                                                    float* __restrict__ out){
    __shared__ float red1[8];
    __shared__ float red2[8];
    const int t = threadIdx.x;
    const size_t tok = blockIdx.x;

    float xv[4];
#pragma unroll
    for (int i = 0; i < 4; i++){
        int c = t + i*256;
        float v = g_lin[tok*HID + c];
        float ge = 0.5f * v * (1.0f + erff(v * 0.70710678118654752f));
        xv[i] = ge + resid[tok*HID + c];
    }
    float s = xv[0] + xv[1] + xv[2] + xv[3];
#pragma unroll
    for (int off = 16; off; off >>= 1) s += __shfl_xor_sync(0xffffffffu, s, off);
    if ((t & 31) == 0) red1[t >> 5] = s;
    __syncthreads();
    float mu = (red1[0]+red1[1]+red1[2]+red1[3]+red1[4]+red1[5]+red1[6]+red1[7]) * (1.0f/HID);
    float v2 = 0.f;
#pragma unroll
    for (int i = 0; i < 4; i++){ float d = xv[i] - mu; v2 += d*d; }
#pragma unroll
    for (int off = 16; off; off >>= 1) v2 += __shfl_xor_sync(0xffffffffu, v2, off);
    if ((t & 31) == 0) red2[t >> 5] = v2;
    __syncthreads();
    float var = (red2[0]+red2[1]+red2[2]+red2[3]+red2[4]+red2[5]+red2[6]+red2[7]) * (1.0f/HID);
    float rstd = rsqrtf(var + 1e-5f);
#pragma unroll
    for (int i = 0; i < 4; i++){
        int c = t + i*256;
        out[tok*HID + c] = (xv[i] - mu) * rstd * gamma[c] + beta[c];
    }
}

// ---------------- launch --------------------------------------------------------
extern "C" void kernel_launch(void* const* d_in, const int* in_sizes, int n_in,
                              void* d_out, int out_size) {
    const float* input_embed = (const float*)d_in[0];
    const float* kg_embed    = (const float*)d_in[1];
    // d_in[2] input_mask: per-row constant additive shift -> softmax-invariant, unused
    const float* kg_mask     = (const float*)d_in[3];
    const float* Wq          = (const float*)d_in[4];
    const float* Wk          = (const float*)d_in[5];
    const float* Wv          = (const float*)d_in[6];
    const float* W_lin       = (const float*)d_in[7];
    const float* b_lin       = (const float*)d_in[8];
    const float* ln_gamma    = (const float*)d_in[9];
    const float* ln_beta     = (const float*)d_in[10];
    float* out = (float*)d_out;

    const int attn_smem = 36992;  // 8K Q + 8K K + 16K V + 4K mask + pad
    const int lin_smem  = 65536;
    cudaFuncSetAttribute(attn_kernel, cudaFuncAttributeMaxDynamicSharedMemorySize, attn_smem);
    cudaFuncSetAttribute(lin_kernel,  cudaFuncAttributeMaxDynamicSharedMemorySize, lin_smem);

    wconv_kernel <<<HID*HID/1024, 256>>>(W_lin);
    qproj_kernel <<<(BB*LQ*NH)/128, 256>>>(input_embed, Wq);
    kvproj_kernel<<<(BB*LK*NH)/128, 256>>>(kg_embed, Wk, Wv);
    attn_kernel  <<<dim3(LQ/128, NH, BB), 128, attn_smem>>>(kg_mask);
    lin_kernel   <<<dim3(HID/128, (BB*LQ)/128), 256, lin_smem>>>(b_lin);
    final_kernel <<<BB*LQ, 256>>>(input_embed, ln_gamma, ln_beta, out);
}

// round 11
// speedup vs baseline: 1.0094x; 1.0094x over previous
#include <cuda_runtime.h>
#include <cuda_bf16.h>
#include <cuda_fp16.h>
#include <cstdint>
#include <math.h>

#define BB 8
#define LQ 512
#define LK 2048
#define NH 16
#define HID 1024
#define NT (LK/64)   // 32 key tiles

using bf16  = __nv_bfloat16;
using bf162 = __nv_bfloat162;

#define LOG2E 1.4426950408889634f

// ---------------- scratch ----------------
__device__ __half g_q  [BB*LQ*HID];
__device__ __half g_k  [BB*LK*HID];
__device__ __half g_v  [BB*LK*HID];
__device__ __half g_ctx[BB*LQ*HID];
__device__ __half g_wl [HID*HID];
__device__ float  g_lin[BB*LQ*HID];

// ---------------- helpers ----------------
__device__ __forceinline__ unsigned sptr(const void* p){
    return (unsigned)__cvta_generic_to_shared(p);
}
__device__ __forceinline__ void ldsm4(unsigned a, unsigned& r0, unsigned& r1, unsigned& r2, unsigned& r3){
    asm volatile("ldmatrix.sync.aligned.m8n8.x4.shared.b16 {%0,%1,%2,%3},[%4];"
                 : "=r"(r0),"=r"(r1),"=r"(r2),"=r"(r3) : "r"(a));
}
__device__ __forceinline__ void ldsm4t(unsigned a, unsigned& r0, unsigned& r1, unsigned& r2, unsigned& r3){
    asm volatile("ldmatrix.sync.aligned.m8n8.x4.trans.shared.b16 {%0,%1,%2,%3},[%4];"
                 : "=r"(r0),"=r"(r1),"=r"(r2),"=r"(r3) : "r"(a));
}
__device__ __forceinline__ void mma_bf16(float* c, const unsigned* a, unsigned b0, unsigned b1){
    asm volatile("mma.sync.aligned.m16n8k16.row.col.f32.bf16.bf16.f32 "
                 "{%0,%1,%2,%3},{%4,%5,%6,%7},{%8,%9},{%0,%1,%2,%3};"
                 : "+f"(c[0]),"+f"(c[1]),"+f"(c[2]),"+f"(c[3])
                 : "r"(a[0]),"r"(a[1]),"r"(a[2]),"r"(a[3]),"r"(b0),"r"(b1));
}
// f16 operands, f16 accumulators (2 regs, packed f16x2)
__device__ __forceinline__ void mma_f16c(unsigned* d, const unsigned* a, unsigned b0, unsigned b1){
    asm volatile("mma.sync.aligned.m16n8k16.row.col.f16.f16.f16.f16 "
                 "{%0,%1},{%2,%3,%4,%5},{%6,%7},{%0,%1};"
                 : "+r"(d[0]),"+r"(d[1])
                 : "r"(a[0]),"r"(a[1]),"r"(a[2]),"r"(a[3]),"r"(b0),"r"(b1));
}
__device__ __forceinline__ void cp16(void* dst, const void* src){
    asm volatile("cp.async.cg.shared.global [%0],[%1],16;" :: "r"(sptr(dst)),"l"(src));
}
__device__ __forceinline__ void cp_commit(){ asm volatile("cp.async.commit_group;"); }
__device__ __forceinline__ void cp_wait1(){ asm volatile("cp.async.wait_group 1;"); }
__device__ __forceinline__ void st_sw4(bf16* s, int row, int c4, float4 f){
    bf162 lo = __floats2bfloat162_rn(f.x, f.y);
    bf162 hi = __floats2bfloat162_rn(f.z, f.w);
    int chunk = c4 >> 1, half = c4 & 1;
    uint2 v = make_uint2(*reinterpret_cast<unsigned*>(&lo), *reinterpret_cast<unsigned*>(&hi));
    *reinterpret_cast<uint2*>(s + row*64 + ((chunk ^ (row & 7)) << 3) + half*4) = v;
}

// ---------------- W_lin fp32 -> f16 prepass ----------------
__global__ __launch_bounds__(256) void wconv_kernel(const float* __restrict__ W){
    int i = (blockIdx.x*256 + threadIdx.x)*4;
    float4 v = *(const float4*)(W + i);
    __half2 lo = __floats2half2_rn(v.x, v.y);
    __half2 hi = __floats2half2_rn(v.z, v.w);
    *(uint2*)(g_wl + i) = make_uint2(*reinterpret_cast<unsigned*>(&lo), *reinterpret_cast<unsigned*>(&hi));
}

// ---------------- Q projection: q = (x @ Wq^T) * 0.125 * log2(e), f16 out -------
__global__ __launch_bounds__(256) void qproj_kernel(const float* __restrict__ x,
                                                    const float* __restrict__ Wq){
    __shared__ bf16 sX[128*64];
    __shared__ bf16 sW[64*64];
    const int t = threadIdx.x, lane = t & 31, w = t >> 5;
    const int rbase = blockIdx.x * 128;
#pragma unroll
    for (int it = 0; it < 8; it++){
        int idx = it*256 + t, row = idx >> 4, c4 = idx & 15;
        st_sw4(sX, row, c4, *(const float4*)(x + (size_t)(rbase+row)*64 + c4*4));
    }
#pragma unroll
    for (int it = 0; it < 4; it++){
        int idx = it*256 + t, row = idx >> 4, c4 = idx & 15;
        st_sw4(sW, row, c4, *(const float4*)(Wq + row*64 + c4*4));
    }
    __syncthreads();
    float acc[8][4] = {};
    const int rA  = w*16 + (lane & 7) + (lane & 8);
    const int rB0 = (lane & 7) + ((lane & 16) >> 1);
#pragma unroll
    for (int kk = 0; kk < 4; kk++){
        unsigned af[4];
        int cA = 2*kk + (lane >> 4);
        ldsm4(sptr(sX + rA*64 + ((cA ^ (rA & 7)) << 3)), af[0], af[1], af[2], af[3]);
        int cB = 2*kk + ((lane >> 3) & 1);
#pragma unroll
        for (int jp = 0; jp < 4; jp++){
            int r = jp*16 + rB0;
            unsigned b0, b1, b2, b3;
            ldsm4(sptr(sW + r*64 + ((cB ^ (r & 7)) << 3)), b0, b1, b2, b3);
            mma_bf16(acc[2*jp],   af, b0, b1);
            mma_bf16(acc[2*jp+1], af, b2, b3);
        }
    }
    const float qs = 0.125f * LOG2E;
    const int g = lane >> 2, cc = (lane & 3)*2;
#pragma unroll
    for (int j = 0; j < 8; j++){
        size_t r0 = (size_t)(rbase + w*16 + g)*64 + j*8 + cc;
        *(__half2*)(g_q + r0)       = __floats2half2_rn(acc[j][0]*qs, acc[j][1]*qs);
        *(__half2*)(g_q + r0 + 512) = __floats2half2_rn(acc[j][2]*qs, acc[j][3]*qs);
    }
}

// ---------------- K/V projection (mma), f16 out ----------------
__global__ __launch_bounds__(256) void kvproj_kernel(const float* __restrict__ x,
                                                     const float* __restrict__ Wk,
                                                     const float* __restrict__ Wv){
    __shared__ bf16 sX [128*64];
    __shared__ bf16 sWk[64*64];
    __shared__ bf16 sWv[64*64];
    const int t = threadIdx.x, lane = t & 31, w = t >> 5;
    const int rbase = blockIdx.x * 128;
#pragma unroll
    for (int it = 0; it < 8; it++){
        int idx = it*256 + t, row = idx >> 4, c4 = idx & 15;
        st_sw4(sX, row, c4, *(const float4*)(x + (size_t)(rbase+row)*64 + c4*4));
    }
#pragma unroll
    for (int it = 0; it < 4; it++){
        int idx = it*256 + t, row = idx >> 4, c4 = idx & 15;
        st_sw4(sWk, row, c4, *(const float4*)(Wk + row*64 + c4*4));
        st_sw4(sWv, row, c4, *(const float4*)(Wv + row*64 + c4*4));
    }
    __syncthreads();
    float ak[8][4] = {}, av[8][4] = {};
    const int rA  = w*16 + (lane & 7) + (lane & 8);
    const int rB0 = (lane & 7) + ((lane & 16) >> 1);
#pragma unroll
    for (int kk = 0; kk < 4; kk++){
        unsigned af[4];
        int cA = 2*kk + (lane >> 4);
        ldsm4(sptr(sX + rA*64 + ((cA ^ (rA & 7)) << 3)), af[0], af[1], af[2], af[3]);
        int cB = 2*kk + ((lane >> 3) & 1);
#pragma unroll
        for (int jp = 0; jp < 4; jp++){
            int r = jp*16 + rB0;
            unsigned b0, b1, b2, b3;
            ldsm4(sptr(sWk + r*64 + ((cB ^ (r & 7)) << 3)), b0, b1, b2, b3);
            mma_bf16(ak[2*jp],   af, b0, b1);
            mma_bf16(ak[2*jp+1], af, b2, b3);
            ldsm4(sptr(sWv + r*64 + ((cB ^ (r & 7)) << 3)), b0, b1, b2, b3);
            mma_bf16(av[2*jp],   af, b0, b1);
            mma_bf16(av[2*jp+1], af, b2, b3);
        }
    }
    const int g = lane >> 2, cc = (lane & 3)*2;
#pragma unroll
    for (int j = 0; j < 8; j++){
        size_t r0 = (size_t)(rbase + w*16 + g)*64 + j*8 + cc;
        *(__half2*)(g_k + r0)       = __floats2half2_rn(ak[j][0], ak[j][1]);
        *(__half2*)(g_k + r0 + 512) = __floats2half2_rn(ak[j][2], ak[j][3]);
        *(__half2*)(g_v + r0)       = __floats2half2_rn(av[j][0], av[j][1]);
        *(__half2*)(g_v + r0 + 512) = __floats2half2_rn(av[j][2], av[j][3]);
    }
}

// ---------------- flash attention: all-f16 MMAs, f16 accumulators ---------------
// grid (LQ/128, NH, BB), 128 threads, 4 CTAs/SM (carveout=100%).
__global__ __launch_bounds__(128, 4) void attn_kernel(const float* __restrict__ kg_mask){
    extern __shared__ char sm[];
    __half* sQ  = (__half*)sm;             // 128x64 = 16KB
    __half* sK  = (__half*)(sm + 16384);   // 2 x 64x64 = 16KB
    __half* sV  = (__half*)(sm + 32768);   // 2 x 64x64 = 16KB
    __half* skb = (__half*)(sm + 49152);   // 2048 halves = 4KB

    const int t = threadIdx.x, lane = t & 31, w = t >> 5;
    const int qt = blockIdx.x, h = blockIdx.y, b = blockIdx.z;

    auto issue = [&](int kt, int buf){
        __half* dk = sK + buf*4096;
        __half* dv = sV + buf*4096;
        const __half* gk = g_k + (size_t)(b*LK + kt*64)*HID + h*64;
        const __half* gv = g_v + (size_t)(b*LK + kt*64)*HID + h*64;
#pragma unroll
        for (int it = 0; it < 4; it++){
            int idx = it*128 + t, rr = idx >> 3, c = idx & 7;
            unsigned so = rr*64 + ((c ^ (rr & 7)) << 3);
            cp16(dk + so, gk + (size_t)rr*HID + c*8);
            cp16(dv + so, gv + (size_t)rr*HID + c*8);
        }
        cp_commit();
    };

    issue(0, 0);
    issue(1, 1);

    // mask bias (log2 domain; any huge negative saturates exp2 to 0 in f16)
    for (int i = t; i < LK; i += 128)
        skb[i] = __float2half((1.0f - kg_mask[b*LK + i]) * (-30000.0f));
    // Q tile
#pragma unroll
    for (int it = 0; it < 8; it++){
        int idx = it*128 + t, row = idx >> 3, c = idx & 7;
        *(uint4*)(sQ + row*64 + ((c ^ (row & 7)) << 3)) =
            *(const uint4*)(g_q + (size_t)(b*LQ + qt*128 + row)*HID + h*64 + c*8);
    }
    __syncthreads();

    // resident Q fragments: 2 rowgroups x 4 k-chunks
    unsigned qf[2][4][4];
#pragma unroll
    for (int rg = 0; rg < 2; rg++){
        int r = w*32 + rg*16 + (lane & 7) + (lane & 8);
#pragma unroll
        for (int kk = 0; kk < 4; kk++){
            int c = 2*kk + (lane >> 4);
            ldsm4(sptr(sQ + r*64 + ((c ^ (r & 7)) << 3)),
                  qf[rg][kk][0], qf[rg][kk][1], qf[rg][kk][2], qf[rg][kk][3]);
        }
    }

    unsigned O2[2][8][2] = {};                   // f16x2 accumulators
    unsigned lacc[2][2] = {};                    // f16x2 row-sums
    const unsigned ONESH = 0x3C003C00u;          // f16x2 {1,1}
    const int rB0 = (lane & 7) + ((lane & 16) >> 1);
    const int rV0 = (lane & 7) + (lane & 8);

    for (int kt = 0; kt < NT; kt++){
        cp_wait1();
        __syncthreads();
        __half* K = sK + (kt & 1)*4096;
        __half* V = sV + (kt & 1)*4096;

#pragma unroll
        for (int hk = 0; hk < 2; hk++){
            // ---- S = Q K^T (f16 accum), 32 keys ----
            unsigned S2[2][4][2] = {};
#pragma unroll
            for (int kk = 0; kk < 4; kk++){
                int cB = 2*kk + ((lane >> 3) & 1);
#pragma unroll
                for (int jp = 0; jp < 2; jp++){
                    int r = hk*32 + jp*16 + rB0;
                    unsigned b0, b1, b2, b3;
                    ldsm4(sptr(K + r*64 + ((cB ^ (r & 7)) << 3)), b0, b1, b2, b3);
                    mma_f16c(S2[0][2*jp],   qf[0][kk], b0, b1);
                    mma_f16c(S2[0][2*jp+1], qf[0][kk], b2, b3);
                    mma_f16c(S2[1][2*jp],   qf[1][kk], b0, b1);
                    mma_f16c(S2[1][2*jp+1], qf[1][kk], b2, b3);
                }
            }

            // ---- p = 2^(S + bias), in place (P fragment == S registers) ----
            const __half2* kb2 = (const __half2*)(skb + kt*64 + hk*32);
#pragma unroll
            for (int rg = 0; rg < 2; rg++){
#pragma unroll
                for (int j = 0; j < 4; j++){
                    __half2 bias = kb2[j*4 + (lane & 3)];
                    __half2 s0 = *(__half2*)&S2[rg][j][0];
                    __half2 s1 = *(__half2*)&S2[rg][j][1];
                    s0 = h2exp2(__hadd2(s0, bias));
                    s1 = h2exp2(__hadd2(s1, bias));
                    S2[rg][j][0] = *(unsigned*)&s0;
                    S2[rg][j][1] = *(unsigned*)&s1;
                }
            }

            // ---- O += P V ; l += P @ ones ----
#pragma unroll
            for (int kk2 = 0; kk2 < 2; kk2++){
                int r = hk*32 + kk2*16 + rV0;
                mma_f16c(lacc[0], &S2[0][2*kk2][0], ONESH, ONESH);
                mma_f16c(lacc[1], &S2[1][2*kk2][0], ONESH, ONESH);
#pragma unroll
                for (int jp = 0; jp < 4; jp++){
                    int c = 2*jp + (lane >> 4);
                    unsigned v0, v1, v2, v3;
                    ldsm4t(sptr(V + r*64 + ((c ^ (r & 7)) << 3)), v0, v1, v2, v3);
                    mma_f16c(O2[0][2*jp],   &S2[0][2*kk2][0], v0, v1);
                    mma_f16c(O2[0][2*jp+1], &S2[0][2*kk2][0], v2, v3);
                    mma_f16c(O2[1][2*jp],   &S2[1][2*kk2][0], v0, v1);
                    mma_f16c(O2[1][2*jp+1], &S2[1][2*kk2][0], v2, v3);
                }
            }
        }

        __syncthreads();
        if (kt + 2 < NT) issue(kt + 2, kt & 1);
        else cp_commit();
    }

    // epilogue: normalize by row sums (f32 divide), store ctx f16
    const int g = lane >> 2, cc = (lane & 3)*2;
#pragma unroll
    for (int rg = 0; rg < 2; rg++){
        float l0 = __low2float(*(__half2*)&lacc[rg][0]);
        float l1 = __low2float(*(__half2*)&lacc[rg][1]);
        float inv0 = 1.0f / l0, inv1 = 1.0f / l1;
#pragma unroll
        for (int j = 0; j < 8; j++){
            float2 a = __half22float2(*(__half2*)&O2[rg][j][0]);
            float2 c = __half22float2(*(__half2*)&O2[rg][j][1]);
            size_t r0 = (size_t)(b*LQ + qt*128 + w*32 + rg*16 + g)*HID + h*64 + j*8 + cc;
            *(__half2*)(g_ctx + r0)         = __floats2half2_rn(a.x*inv0, a.y*inv0);
            *(__half2*)(g_ctx + r0 + 8*HID) = __floats2half2_rn(c.x*inv1, c.y*inv1);
        }
    }
}

// ---------------- output linear: f16 MMA, f16 accum, double buffer --------------
__global__ __launch_bounds__(256) void lin_kernel(const float* __restrict__ bias){
    extern __shared__ char sm[];
    __half* sA = (__half*)sm;            // 2 x 128x64 = 32KB
    __half* sW = (__half*)(sm + 32768);  // 2 x 128x64 = 32KB
    const int t = threadIdx.x, lane = t & 31, w = t >> 5;
    const int ct = blockIdx.x, rt = blockIdx.y;
    const int wrow = (w >> 1)*32, wcol = (w & 1)*64;

    auto issue = [&](int ki, int buf){
        __half* da = sA + buf*8192;
        __half* dw = sW + buf*8192;
#pragma unroll
        for (int it = 0; it < 4; it++){
            int idx = it*256 + t, row = idx >> 3, c = idx & 7;
            unsigned so = row*64 + ((c ^ (row & 7)) << 3);
            cp16(da + so, g_ctx + (size_t)(rt*128 + row)*HID + ki*64 + c*8);
            cp16(dw + so, g_wl  + (size_t)(ct*128 + row)*HID + ki*64 + c*8);
        }
        cp_commit();
    };

    issue(0, 0);
    issue(1, 1);

    unsigned acc2[2][8][2] = {};
    const int rB0 = (lane & 7) + ((lane & 16) >> 1);

    for (int ki = 0; ki < HID/64; ki++){
        cp_wait1();
        __syncthreads();
        __half* A  = sA + (ki & 1)*8192;
        __half* Wt = sW + (ki & 1)*8192;
#pragma unroll
        for (int kk = 0; kk < 4; kk++){
            unsigned af0[4], af1[4];
            int cA = 2*kk + (lane >> 4);
            int rA0 = wrow + (lane & 7) + (lane & 8);
            int rA1 = rA0 + 16;
            ldsm4(sptr(A + rA0*64 + ((cA ^ (rA0 & 7)) << 3)), af0[0], af0[1], af0[2], af0[3]);
            ldsm4(sptr(A + rA1*64 + ((cA ^ (rA1 & 7)) << 3)), af1[0], af1[1], af1[2], af1[3]);
            int cB = 2*kk + ((lane >> 3) & 1);
#pragma unroll
            for (int jp = 0; jp < 4; jp++){
                int r = wcol + jp*16 + rB0;
                unsigned b0, b1, b2, b3;
                ldsm4(sptr(Wt + r*64 + ((cB ^ (r & 7)) << 3)), b0, b1, b2, b3);
                mma_f16c(acc2[0][2*jp],   af0, b0, b1);
                mma_f16c(acc2[0][2*jp+1], af0, b2, b3);
                mma_f16c(acc2[1][2*jp],   af1, b0, b1);
                mma_f16c(acc2[1][2*jp+1], af1, b2, b3);
            }
        }
        __syncthreads();
        if (ki + 2 < HID/64) issue(ki + 2, ki & 1);
        else cp_commit();
    }

    const int g = lane >> 2, cc = (lane & 3)*2;
#pragma unroll
    for (int rg = 0; rg < 2; rg++){
#pragma unroll
        for (int j = 0; j < 8; j++){
            int col = ct*128 + wcol + j*8 + cc;
            float2 bv = *(const float2*)(bias + col);
            float2 a = __half22float2(*(__half2*)&acc2[rg][j][0]);
            float2 c = __half22float2(*(__half2*)&acc2[rg][j][1]);
            size_t r0 = (size_t)(rt*128 + wrow + rg*16 + g)*HID + col;
            *(float2*)(g_lin + r0)         = make_float2(a.x + bv.x, a.y + bv.y);
            *(float2*)(g_lin + r0 + 8*HID) = make_float2(c.x + bv.x, c.y + bv.y);
        }
    }
}

// ---------------- gelu + residual + layernorm ----------------------------------
__global__ __launch_bounds__(256) void final_kernel(const float* __restrict__ resid,
                                                    const float* __restrict__ gamma,
                                                    const float* __restrict__ beta,
                                                    float* __restrict__ out){
    __shared__ float red1[8];
    __shared__ float red2[8];
    const int t = threadIdx.x;
    const size_t tok = blockIdx.x;

    float xv[4];
#pragma unroll
    for (int i = 0; i < 4; i++){
        int c = t + i*256;
        float v = g_lin[tok*HID + c];
        float ge = 0.5f * v * (1.0f + erff(v * 0.70710678118654752f));
        xv[i] = ge + resid[tok*HID + c];
    }
    float s = xv[0] + xv[1] + xv[2] + xv[3];
#pragma unroll
    for (int off = 16; off; off >>= 1) s += __shfl_xor_sync(0xffffffffu, s, off);
    if ((t & 31) == 0) red1[t >> 5] = s;
    __syncthreads();
    float mu = (red1[0]+red1[1]+red1[2]+red1[3]+red1[4]+red1[5]+red1[6]+red1[7]) * (1.0f/HID);
    float v2 = 0.f;
#pragma unroll
    for (int i = 0; i < 4; i++){ float d = xv[i] - mu; v2 += d*d; }
#pragma unroll
    for (int off = 16; off; off >>= 1) v2 += __shfl_xor_sync(0xffffffffu, v2, off);
    if ((t & 31) == 0) red2[t >> 5] = v2;
    __syncthreads();
    float var = (red2[0]+red2[1]+red2[2]+red2[3]+red2[4]+red2[5]+red2[6]+red2[7]) * (1.0f/HID);
    float rstd = rsqrtf(var + 1e-5f);
#pragma unroll
    for (int i = 0; i < 4; i++){
        int c = t + i*256;
        out[tok*HID + c] = (xv[i] - mu) * rstd * gamma[c] + beta[c];
    }
}

// ---------------- launch --------------------------------------------------------
extern "C" void kernel_launch(void* const* d_in, const int* in_sizes, int n_in,
                              void* d_out, int out_size) {
    const float* input_embed = (const float*)d_in[0];
    const float* kg_embed    = (const float*)d_in[1];
    // d_in[2] input_mask: per-row constant additive shift -> softmax-invariant, unused
    const float* kg_mask     = (const float*)d_in[3];
    const float* Wq          = (const float*)d_in[4];
    const float* Wk          = (const float*)d_in[5];
    const float* Wv          = (const float*)d_in[6];
    const float* W_lin       = (const float*)d_in[7];
    const float* b_lin       = (const float*)d_in[8];
    const float* ln_gamma    = (const float*)d_in[9];
    const float* ln_beta     = (const float*)d_in[10];
    float* out = (float*)d_out;

    const int attn_smem = 53248;  // 52KB; carveout 100% -> 4 CTAs/SM
    const int lin_smem  = 65536;  // 64KB; carveout 100% -> 3 CTAs/SM
    cudaFuncSetAttribute(attn_kernel, cudaFuncAttributeMaxDynamicSharedMemorySize, attn_smem);
    cudaFuncSetAttribute(lin_kernel,  cudaFuncAttributeMaxDynamicSharedMemorySize, lin_smem);
    // KEY: default carveout silently caps residency at ~1 CTA/SM; request full smem pool
    cudaFuncSetAttribute(attn_kernel, cudaFuncAttributePreferredSharedMemoryCarveout, 100);
    cudaFuncSetAttribute(lin_kernel,  cudaFuncAttributePreferredSharedMemoryCarveout, 100);
    cudaFuncSetAttribute(qproj_kernel, cudaFuncAttributePreferredSharedMemoryCarveout, 100);
    cudaFuncSetAttribute(kvproj_kernel, cudaFuncAttributePreferredSharedMemoryCarveout, 100);

    wconv_kernel <<<HID*HID/1024, 256>>>(W_lin);
    qproj_kernel <<<(BB*LQ*NH)/128, 256>>>(input_embed, Wq);
    kvproj_kernel<<<(BB*LK*NH)/128, 256>>>(kg_embed, Wk, Wv);
    attn_kernel  <<<dim3(LQ/128, NH, BB), 128, attn_smem>>>(kg_mask);
    lin_kernel   <<<dim3(HID/128, (BB*LQ)/128), 256, lin_smem>>>(b_lin);
    final_kernel <<<BB*LQ, 256>>>(input_embed, ln_gamma, ln_beta, out);
}

// round 12
// speedup vs baseline: 1.0298x; 1.0203x over previous
#include <cuda_runtime.h>
#include <cuda_bf16.h>
#include <cuda_fp16.h>
#include <cstdint>
#include <math.h>

#define BB 8
#define LQ 512
#define LK 2048
#define NH 16
#define HID 1024
#define NT (LK/64)   // 32 key tiles

using bf16  = __nv_bfloat16;
using bf162 = __nv_bfloat162;

#define LOG2E 1.4426950408889634f

// ---------------- scratch ----------------
__device__ __half g_q  [BB*LQ*HID];
__device__ __half g_k  [BB*LK*HID];
__device__ __half g_v  [BB*LK*HID];
__device__ __half g_ctx[BB*LQ*HID];
__device__ __half g_wl [HID*HID];
__device__ float  g_lin[BB*LQ*HID];

// ---------------- helpers ----------------
__device__ __forceinline__ unsigned sptr(const void* p){
    return (unsigned)__cvta_generic_to_shared(p);
}
__device__ __forceinline__ void ldsm4(unsigned a, unsigned& r0, unsigned& r1, unsigned& r2, unsigned& r3){
    asm volatile("ldmatrix.sync.aligned.m8n8.x4.shared.b16 {%0,%1,%2,%3},[%4];"
                 : "=r"(r0),"=r"(r1),"=r"(r2),"=r"(r3) : "r"(a));
}
__device__ __forceinline__ void ldsm4t(unsigned a, unsigned& r0, unsigned& r1, unsigned& r2, unsigned& r3){
    asm volatile("ldmatrix.sync.aligned.m8n8.x4.trans.shared.b16 {%0,%1,%2,%3},[%4];"
                 : "=r"(r0),"=r"(r1),"=r"(r2),"=r"(r3) : "r"(a));
}
__device__ __forceinline__ void mma_bf16(float* c, const unsigned* a, unsigned b0, unsigned b1){
    asm volatile("mma.sync.aligned.m16n8k16.row.col.f32.bf16.bf16.f32 "
                 "{%0,%1,%2,%3},{%4,%5,%6,%7},{%8,%9},{%0,%1,%2,%3};"
                 : "+f"(c[0]),"+f"(c[1]),"+f"(c[2]),"+f"(c[3])
                 : "r"(a[0]),"r"(a[1]),"r"(a[2]),"r"(a[3]),"r"(b0),"r"(b1));
}
// f16 operands, f16 accumulators (2 regs, packed f16x2)
__device__ __forceinline__ void mma_f16c(unsigned* d, const unsigned* a, unsigned b0, unsigned b1){
    asm volatile("mma.sync.aligned.m16n8k16.row.col.f16.f16.f16.f16 "
                 "{%0,%1},{%2,%3,%4,%5},{%6,%7},{%0,%1};"
                 : "+r"(d[0]),"+r"(d[1])
                 : "r"(a[0]),"r"(a[1]),"r"(a[2]),"r"(a[3]),"r"(b0),"r"(b1));
}
__device__ __forceinline__ void cp16(void* dst, const void* src){
    asm volatile("cp.async.cg.shared.global [%0],[%1],16;" :: "r"(sptr(dst)),"l"(src));
}
__device__ __forceinline__ void cp_commit(){ asm volatile("cp.async.commit_group;"); }
__device__ __forceinline__ void cp_wait1(){ asm volatile("cp.async.wait_group 1;"); }
__device__ __forceinline__ void st_sw4(bf16* s, int row, int c4, float4 f){
    bf162 lo = __floats2bfloat162_rn(f.x, f.y);
    bf162 hi = __floats2bfloat162_rn(f.z, f.w);
    int chunk = c4 >> 1, half = c4 & 1;
    uint2 v = make_uint2(*reinterpret_cast<unsigned*>(&lo), *reinterpret_cast<unsigned*>(&hi));
    *reinterpret_cast<uint2*>(s + row*64 + ((chunk ^ (row & 7)) << 3) + half*4) = v;
}

// ---------------- W_lin fp32 -> f16 prepass ----------------
__global__ __launch_bounds__(256) void wconv_kernel(const float* __restrict__ W){
    int i = (blockIdx.x*256 + threadIdx.x)*4;
    float4 v = *(const float4*)(W + i);
    __half2 lo = __floats2half2_rn(v.x, v.y);
    __half2 hi = __floats2half2_rn(v.z, v.w);
    *(uint2*)(g_wl + i) = make_uint2(*reinterpret_cast<unsigned*>(&lo), *reinterpret_cast<unsigned*>(&hi));
}

// ---------------- Q projection: q = (x @ Wq^T) * 0.125 * log2(e), f16 out -------
__global__ __launch_bounds__(256) void qproj_kernel(const float* __restrict__ x,
                                                    const float* __restrict__ Wq){
    __shared__ bf16 sX[128*64];
    __shared__ bf16 sW[64*64];
    const int t = threadIdx.x, lane = t & 31, w = t >> 5;
    const int rbase = blockIdx.x * 128;
#pragma unroll
    for (int it = 0; it < 8; it++){
        int idx = it*256 + t, row = idx >> 4, c4 = idx & 15;
        st_sw4(sX, row, c4, *(const float4*)(x + (size_t)(rbase+row)*64 + c4*4));
    }
#pragma unroll
    for (int it = 0; it < 4; it++){
        int idx = it*256 + t, row = idx >> 4, c4 = idx & 15;
        st_sw4(sW, row, c4, *(const float4*)(Wq + row*64 + c4*4));
    }
    __syncthreads();
    float acc[8][4] = {};
    const int rA  = w*16 + (lane & 7) + (lane & 8);
    const int rB0 = (lane & 7) + ((lane & 16) >> 1);
#pragma unroll
    for (int kk = 0; kk < 4; kk++){
        unsigned af[4];
        int cA = 2*kk + (lane >> 4);
        ldsm4(sptr(sX + rA*64 + ((cA ^ (rA & 7)) << 3)), af[0], af[1], af[2], af[3]);
        int cB = 2*kk + ((lane >> 3) & 1);
#pragma unroll
        for (int jp = 0; jp < 4; jp++){
            int r = jp*16 + rB0;
            unsigned b0, b1, b2, b3;
            ldsm4(sptr(sW + r*64 + ((cB ^ (r & 7)) << 3)), b0, b1, b2, b3);
            mma_bf16(acc[2*jp],   af, b0, b1);
            mma_bf16(acc[2*jp+1], af, b2, b3);
        }
    }
    const float qs = 0.125f * LOG2E;
    const int g = lane >> 2, cc = (lane & 3)*2;
#pragma unroll
    for (int j = 0; j < 8; j++){
        size_t r0 = (size_t)(rbase + w*16 + g)*64 + j*8 + cc;
        *(__half2*)(g_q + r0)       = __floats2half2_rn(acc[j][0]*qs, acc[j][1]*qs);
        *(__half2*)(g_q + r0 + 512) = __floats2half2_rn(acc[j][2]*qs, acc[j][3]*qs);
    }
}

// ---------------- K/V projection (mma), f16 out ----------------
__global__ __launch_bounds__(256) void kvproj_kernel(const float* __restrict__ x,
                                                     const float* __restrict__ Wk,
                                                     const float* __restrict__ Wv){
    __shared__ bf16 sX [128*64];
    __shared__ bf16 sWk[64*64];
    __shared__ bf16 sWv[64*64];
    const int t = threadIdx.x, lane = t & 31, w = t >> 5;
    const int rbase = blockIdx.x * 128;
#pragma unroll
    for (int it = 0; it < 8; it++){
        int idx = it*256 + t, row = idx >> 4, c4 = idx & 15;
        st_sw4(sX, row, c4, *(const float4*)(x + (size_t)(rbase+row)*64 + c4*4));
    }
#pragma unroll
    for (int it = 0; it < 4; it++){
        int idx = it*256 + t, row = idx >> 4, c4 = idx & 15;
        st_sw4(sWk, row, c4, *(const float4*)(Wk + row*64 + c4*4));
        st_sw4(sWv, row, c4, *(const float4*)(Wv + row*64 + c4*4));
    }
    __syncthreads();
    float ak[8][4] = {}, av[8][4] = {};
    const int rA  = w*16 + (lane & 7) + (lane & 8);
    const int rB0 = (lane & 7) + ((lane & 16) >> 1);
#pragma unroll
    for (int kk = 0; kk < 4; kk++){
        unsigned af[4];
        int cA = 2*kk + (lane >> 4);
        ldsm4(sptr(sX + rA*64 + ((cA ^ (rA & 7)) << 3)), af[0], af[1], af[2], af[3]);
        int cB = 2*kk + ((lane >> 3) & 1);
#pragma unroll
        for (int jp = 0; jp < 4; jp++){
            int r = jp*16 + rB0;
            unsigned b0, b1, b2, b3;
            ldsm4(sptr(sWk + r*64 + ((cB ^ (r & 7)) << 3)), b0, b1, b2, b3);
            mma_bf16(ak[2*jp],   af, b0, b1);
            mma_bf16(ak[2*jp+1], af, b2, b3);
            ldsm4(sptr(sWv + r*64 + ((cB ^ (r & 7)) << 3)), b0, b1, b2, b3);
            mma_bf16(av[2*jp],   af, b0, b1);
            mma_bf16(av[2*jp+1], af, b2, b3);
        }
    }
    const int g = lane >> 2, cc = (lane & 3)*2;
#pragma unroll
    for (int j = 0; j < 8; j++){
        size_t r0 = (size_t)(rbase + w*16 + g)*64 + j*8 + cc;
        *(__half2*)(g_k + r0)       = __floats2half2_rn(ak[j][0], ak[j][1]);
        *(__half2*)(g_k + r0 + 512) = __floats2half2_rn(ak[j][2], ak[j][3]);
        *(__half2*)(g_v + r0)       = __floats2half2_rn(av[j][0], av[j][1]);
        *(__half2*)(g_v + r0 + 512) = __floats2half2_rn(av[j][2], av[j][3]);
    }
}

// ---------------- flash attention: 64-row q tiles, 1024 CTAs --------------------
// grid (LQ/64, NH, BB), 128 threads = 4 warps x 16 q-rows.
__global__ __launch_bounds__(128, 5) void attn_kernel(const float* __restrict__ kg_mask){
    extern __shared__ char sm[];
    __half* sQ  = (__half*)sm;             // 64x64 = 8KB
    __half* sK  = (__half*)(sm + 8192);    // 2 x 64x64 = 16KB
    __half* sV  = (__half*)(sm + 24576);   // 2 x 64x64 = 16KB
    __half* skb = (__half*)(sm + 40960);   // 2048 halves = 4KB

    const int t = threadIdx.x, lane = t & 31, w = t >> 5;
    const int qt = blockIdx.x, h = blockIdx.y, b = blockIdx.z;

    auto issue = [&](int kt, int buf){
        __half* dk = sK + buf*4096;
        __half* dv = sV + buf*4096;
        const __half* gk = g_k + (size_t)(b*LK + kt*64)*HID + h*64;
        const __half* gv = g_v + (size_t)(b*LK + kt*64)*HID + h*64;
#pragma unroll
        for (int it = 0; it < 4; it++){
            int idx = it*128 + t, rr = idx >> 3, c = idx & 7;
            unsigned so = rr*64 + ((c ^ (rr & 7)) << 3);
            cp16(dk + so, gk + (size_t)rr*HID + c*8);
            cp16(dv + so, gv + (size_t)rr*HID + c*8);
        }
        cp_commit();
    };

    issue(0, 0);
    issue(1, 1);

    // mask bias (log2 domain; huge negative saturates exp2 to 0 in f16)
    for (int i = t; i < LK; i += 128)
        skb[i] = __float2half((1.0f - kg_mask[b*LK + i]) * (-30000.0f));
    // Q tile (64 rows)
#pragma unroll
    for (int it = 0; it < 4; it++){
        int idx = it*128 + t, row = idx >> 3, c = idx & 7;
        *(uint4*)(sQ + row*64 + ((c ^ (row & 7)) << 3)) =
            *(const uint4*)(g_q + (size_t)(b*LQ + qt*64 + row)*HID + h*64 + c*8);
    }
    __syncthreads();

    // resident Q fragments: 4 k-chunks (16 rows per warp)
    unsigned qf[4][4];
    {
        int r = w*16 + (lane & 7) + (lane & 8);
#pragma unroll
        for (int kk = 0; kk < 4; kk++){
            int c = 2*kk + (lane >> 4);
            ldsm4(sptr(sQ + r*64 + ((c ^ (r & 7)) << 3)),
                  qf[kk][0], qf[kk][1], qf[kk][2], qf[kk][3]);
        }
    }

    unsigned O2[8][2] = {};                      // f16x2 accumulators
    unsigned lacc[2] = {};                       // f16x2 row-sums (rows g, g+8)
    const unsigned ONESH = 0x3C003C00u;
    const int rB0 = (lane & 7) + ((lane & 16) >> 1);
    const int rV0 = (lane & 7) + (lane & 8);

    for (int kt = 0; kt < NT; kt++){
        cp_wait1();
        __syncthreads();
        __half* K = sK + (kt & 1)*4096;
        __half* V = sV + (kt & 1)*4096;

        // ---- S = Q K^T (f16 accum), full 64 keys ----
        unsigned S2[8][2] = {};
#pragma unroll
        for (int kk = 0; kk < 4; kk++){
            int cB = 2*kk + ((lane >> 3) & 1);
#pragma unroll
            for (int jp = 0; jp < 4; jp++){
                int r = jp*16 + rB0;
                unsigned b0, b1, b2, b3;
                ldsm4(sptr(K + r*64 + ((cB ^ (r & 7)) << 3)), b0, b1, b2, b3);
                mma_f16c(S2[2*jp],   qf[kk], b0, b1);
                mma_f16c(S2[2*jp+1], qf[kk], b2, b3);
            }
        }

        // ---- p = 2^(S + bias), in place ----
        const __half2* kb2 = (const __half2*)(skb + kt*64);
#pragma unroll
        for (int j = 0; j < 8; j++){
            __half2 bias = kb2[j*4 + (lane & 3)];
            __half2 s0 = *(__half2*)&S2[j][0];
            __half2 s1 = *(__half2*)&S2[j][1];
            s0 = h2exp2(__hadd2(s0, bias));
            s1 = h2exp2(__hadd2(s1, bias));
            S2[j][0] = *(unsigned*)&s0;
            S2[j][1] = *(unsigned*)&s1;
        }

        // ---- O += P V ; l += P @ ones ----
#pragma unroll
        for (int kk2 = 0; kk2 < 4; kk2++){
            int r = kk2*16 + rV0;
            mma_f16c(lacc, &S2[2*kk2][0], ONESH, ONESH);
#pragma unroll
            for (int jp = 0; jp < 4; jp++){
                int c = 2*jp + (lane >> 4);
                unsigned v0, v1, v2, v3;
                ldsm4t(sptr(V + r*64 + ((c ^ (r & 7)) << 3)), v0, v1, v2, v3);
                mma_f16c(O2[2*jp],   &S2[2*kk2][0], v0, v1);
                mma_f16c(O2[2*jp+1], &S2[2*kk2][0], v2, v3);
            }
        }

        __syncthreads();
        if (kt + 2 < NT) issue(kt + 2, kt & 1);
        else cp_commit();
    }

    // epilogue: normalize by row sums (f32 divide), store ctx f16
    const int g = lane >> 2, cc = (lane & 3)*2;
    float l0 = __low2float(*(__half2*)&lacc[0]);    // row g
    float l1 = __low2float(*(__half2*)&lacc[1]);    // row g+8
    float inv0 = 1.0f / l0, inv1 = 1.0f / l1;
#pragma unroll
    for (int j = 0; j < 8; j++){
        float2 a = __half22float2(*(__half2*)&O2[j][0]);
        float2 c = __half22float2(*(__half2*)&O2[j][1]);
        size_t r0 = (size_t)(b*LQ + qt*64 + w*16 + g)*HID + h*64 + j*8 + cc;
        *(__half2*)(g_ctx + r0)         = __floats2half2_rn(a.x*inv0, a.y*inv0);
        *(__half2*)(g_ctx + r0 + 8*HID) = __floats2half2_rn(c.x*inv1, c.y*inv1);
    }
}

// ---------------- output linear + gelu + residual (fused epilogue) --------------
__global__ __launch_bounds__(256) void lin_kernel(const float* __restrict__ bias,
                                                  const float* __restrict__ resid){
    extern __shared__ char sm[];
    __half* sA = (__half*)sm;            // 2 x 128x64 = 32KB
    __half* sW = (__half*)(sm + 32768);  // 2 x 128x64 = 32KB
    const int t = threadIdx.x, lane = t & 31, w = t >> 5;
    const int ct = blockIdx.x, rt = blockIdx.y;
    const int wrow = (w >> 1)*32, wcol = (w & 1)*64;

    auto issue = [&](int ki, int buf){
        __half* da = sA + buf*8192;
        __half* dw = sW + buf*8192;
#pragma unroll
        for (int it = 0; it < 4; it++){
            int idx = it*256 + t, row = idx >> 3, c = idx & 7;
            unsigned so = row*64 + ((c ^ (row & 7)) << 3);
            cp16(da + so, g_ctx + (size_t)(rt*128 + row)*HID + ki*64 + c*8);
            cp16(dw + so, g_wl  + (size_t)(ct*128 + row)*HID + ki*64 + c*8);
        }
        cp_commit();
    };

    issue(0, 0);
    issue(1, 1);

    unsigned acc2[2][8][2] = {};
    const int rB0 = (lane & 7) + ((lane & 16) >> 1);

    for (int ki = 0; ki < HID/64; ki++){
        cp_wait1();
        __syncthreads();
        __half* A  = sA + (ki & 1)*8192;
        __half* Wt = sW + (ki & 1)*8192;
#pragma unroll
        for (int kk = 0; kk < 4; kk++){
            unsigned af0[4], af1[4];
            int cA = 2*kk + (lane >> 4);
            int rA0 = wrow + (lane & 7) + (lane & 8);
            int rA1 = rA0 + 16;
            ldsm4(sptr(A + rA0*64 + ((cA ^ (rA0 & 7)) << 3)), af0[0], af0[1], af0[2], af0[3]);
            ldsm4(sptr(A + rA1*64 + ((cA ^ (rA1 & 7)) << 3)), af1[0], af1[1], af1[2], af1[3]);
            int cB = 2*kk + ((lane >> 3) & 1);
#pragma unroll
            for (int jp = 0; jp < 4; jp++){
                int r = wcol + jp*16 + rB0;
                unsigned b0, b1, b2, b3;
                ldsm4(sptr(Wt + r*64 + ((cB ^ (r & 7)) << 3)), b0, b1, b2, b3);
                mma_f16c(acc2[0][2*jp],   af0, b0, b1);
                mma_f16c(acc2[0][2*jp+1], af0, b2, b3);
                mma_f16c(acc2[1][2*jp],   af1, b0, b1);
                mma_f16c(acc2[1][2*jp+1], af1, b2, b3);
            }
        }
        __syncthreads();
        if (ki + 2 < HID/64) issue(ki + 2, ki & 1);
        else cp_commit();
    }

    // epilogue: x = gelu(lin + bias) + resid  (fused; final kernel does LN only)
    const int g = lane >> 2, cc = (lane & 3)*2;
#pragma unroll
    for (int rg = 0; rg < 2; rg++){
#pragma unroll
        for (int j = 0; j < 8; j++){
            int col = ct*128 + wcol + j*8 + cc;
            float2 bv = *(const float2*)(bias + col);
            float2 a = __half22float2(*(__half2*)&acc2[rg][j][0]);
            float2 c = __half22float2(*(__half2*)&acc2[rg][j][1]);
            size_t row0 = (size_t)(rt*128 + wrow + rg*16 + g);
            float v0 = a.x + bv.x, v1 = a.y + bv.y;
            float v2 = c.x + bv.x, v3 = c.y + bv.y;
            float2 rs0 = *(const float2*)(resid + row0*HID + col);
            float2 rs1 = *(const float2*)(resid + (row0 + 8)*HID + col);
            float g0 = 0.5f*v0*(1.0f + erff(v0*0.70710678f)) + rs0.x;
            float g1 = 0.5f*v1*(1.0f + erff(v1*0.70710678f)) + rs0.y;
            float g2 = 0.5f*v2*(1.0f + erff(v2*0.70710678f)) + rs1.x;
            float g3 = 0.5f*v3*(1.0f + erff(v3*0.70710678f)) + rs1.y;
            *(float2*)(g_lin + row0*HID + col)       = make_float2(g0, g1);
            *(float2*)(g_lin + (row0 + 8)*HID + col) = make_float2(g2, g3);
        }
    }
}

// ---------------- layernorm only ----------------
__global__ __launch_bounds__(256) void final_kernel(const float* __restrict__ gamma,
                                                    const float* __restrict__ beta,
                                                    float* __restrict__ out){
    __shared__ float red1[8];
    __shared__ float red2[8];
    const int t = threadIdx.x;
    const size_t tok = blockIdx.x;

    float xv[4];
#pragma unroll
    for (int i = 0; i < 4; i++)
        xv[i] = g_lin[tok*HID + t + i*256];
    float s = xv[0] + xv[1] + xv[2] + xv[3];
#pragma unroll
    for (int off = 16; off; off >>= 1) s += __shfl_xor_sync(0xffffffffu, s, off);
    if ((t & 31) == 0) red1[t >> 5] = s;
    __syncthreads();
    float mu = (red1[0]+red1[1]+red1[2]+red1[3]+red1[4]+red1[5]+red1[6]+red1[7]) * (1.0f/HID);
    float v2 = 0.f;
#pragma unroll
    for (int i = 0; i < 4; i++){ float d = xv[i] - mu; v2 += d*d; }
#pragma unroll
    for (int off = 16; off; off >>= 1) v2 += __shfl_xor_sync(0xffffffffu, v2, off);
    if ((t & 31) == 0) red2[t >> 5] = v2;
    __syncthreads();
    float var = (red2[0]+red2[1]+red2[2]+red2[3]+red2[4]+red2[5]+red2[6]+red2[7]) * (1.0f/HID);
    float rstd = rsqrtf(var + 1e-5f);
#pragma unroll
    for (int i = 0; i < 4; i++){
        int c = t + i*256;
        out[tok*HID + c] = (xv[i] - mu) * rstd * gamma[c] + beta[c];
    }
}

// ---------------- launch --------------------------------------------------------
extern "C" void kernel_launch(void* const* d_in, const int* in_sizes, int n_in,
                              void* d_out, int out_size) {
    const float* input_embed = (const float*)d_in[0];
    const float* kg_embed    = (const float*)d_in[1];
    // d_in[2] input_mask: per-row constant additive shift -> softmax-invariant, unused
    const float* kg_mask     = (const float*)d_in[3];
    const float* Wq          = (const float*)d_in[4];
    const float* Wk          = (const float*)d_in[5];
    const float* Wv          = (const float*)d_in[6];
    const float* W_lin       = (const float*)d_in[7];
    const float* b_lin       = (const float*)d_in[8];
    const float* ln_gamma    = (const float*)d_in[9];
    const float* ln_beta     = (const float*)d_in[10];
    float* out = (float*)d_out;

    const int attn_smem = 45056;  // 44KB -> 5 CTAs/SM
    const int lin_smem  = 65536;
    cudaFuncSetAttribute(attn_kernel, cudaFuncAttributeMaxDynamicSharedMemorySize, attn_smem);
    cudaFuncSetAttribute(lin_kernel,  cudaFuncAttributeMaxDynamicSharedMemorySize, lin_smem);
    cudaFuncSetAttribute(attn_kernel, cudaFuncAttributePreferredSharedMemoryCarveout, 100);
    cudaFuncSetAttribute(lin_kernel,  cudaFuncAttributePreferredSharedMemoryCarveout, 100);

    wconv_kernel <<<HID*HID/1024, 256>>>(W_lin);
    qproj_kernel <<<(BB*LQ*NH)/128, 256>>>(input_embed, Wq);
    kvproj_kernel<<<(BB*LK*NH)/128, 256>>>(kg_embed, Wk, Wv);
    attn_kernel  <<<dim3(LQ/64, NH, BB), 128, attn_smem>>>(kg_mask);
    lin_kernel   <<<dim3(HID/128, (BB*LQ)/128), 256, lin_smem>>>(b_lin, input_embed);
    final_kernel <<<BB*LQ, 256>>>(ln_gamma, ln_beta, out);
}

// round 13
// speedup vs baseline: 1.0406x; 1.0105x over previous
#include <cuda_runtime.h>
#include <cuda_bf16.h>
#include <cuda_fp16.h>
#include <cstdint>
#include <math.h>

#define BB 8
#define LQ 512
#define LK 2048
#define NH 16
#define HID 1024
#define NT (LK/64)   // 32 key tiles

using bf16  = __nv_bfloat16;
using bf162 = __nv_bfloat162;

#define LOG2E 1.4426950408889634f

// ---------------- scratch ----------------
__device__ __half g_q  [BB*LQ*HID];
__device__ __half g_k  [BB*LK*HID];
__device__ __half g_v  [BB*LK*HID];
__device__ __half g_ctx[BB*LQ*HID];
__device__ __half g_wl [HID*HID];
__device__ float  g_lin[BB*LQ*HID];

// ---------------- helpers ----------------
__device__ __forceinline__ unsigned sptr(const void* p){
    return (unsigned)__cvta_generic_to_shared(p);
}
__device__ __forceinline__ void ldsm4(unsigned a, unsigned& r0, unsigned& r1, unsigned& r2, unsigned& r3){
    asm volatile("ldmatrix.sync.aligned.m8n8.x4.shared.b16 {%0,%1,%2,%3},[%4];"
                 : "=r"(r0),"=r"(r1),"=r"(r2),"=r"(r3) : "r"(a));
}
__device__ __forceinline__ void ldsm4t(unsigned a, unsigned& r0, unsigned& r1, unsigned& r2, unsigned& r3){
    asm volatile("ldmatrix.sync.aligned.m8n8.x4.trans.shared.b16 {%0,%1,%2,%3},[%4];"
                 : "=r"(r0),"=r"(r1),"=r"(r2),"=r"(r3) : "r"(a));
}
__device__ __forceinline__ void mma_bf16(float* c, const unsigned* a, unsigned b0, unsigned b1){
    asm volatile("mma.sync.aligned.m16n8k16.row.col.f32.bf16.bf16.f32 "
                 "{%0,%1,%2,%3},{%4,%5,%6,%7},{%8,%9},{%0,%1,%2,%3};"
                 : "+f"(c[0]),"+f"(c[1]),"+f"(c[2]),"+f"(c[3])
                 : "r"(a[0]),"r"(a[1]),"r"(a[2]),"r"(a[3]),"r"(b0),"r"(b1));
}
// f16 operands, f16 accumulators (2 regs, packed f16x2)
__device__ __forceinline__ void mma_f16c(unsigned* d, const unsigned* a, unsigned b0, unsigned b1){
    asm volatile("mma.sync.aligned.m16n8k16.row.col.f16.f16.f16.f16 "
                 "{%0,%1},{%2,%3,%4,%5},{%6,%7},{%0,%1};"
                 : "+r"(d[0]),"+r"(d[1])
                 : "r"(a[0]),"r"(a[1]),"r"(a[2]),"r"(a[3]),"r"(b0),"r"(b1));
}
__device__ __forceinline__ void cp16(void* dst, const void* src){
    asm volatile("cp.async.cg.shared.global [%0],[%1],16;" :: "r"(sptr(dst)),"l"(src));
}
__device__ __forceinline__ void cp_commit(){ asm volatile("cp.async.commit_group;"); }
__device__ __forceinline__ void cp_wait1(){ asm volatile("cp.async.wait_group 1;"); }
__device__ __forceinline__ void st_sw4(bf16* s, int row, int c4, float4 f){
    bf162 lo = __floats2bfloat162_rn(f.x, f.y);
    bf162 hi = __floats2bfloat162_rn(f.z, f.w);
    int chunk = c4 >> 1, half = c4 & 1;
    uint2 v = make_uint2(*reinterpret_cast<unsigned*>(&lo), *reinterpret_cast<unsigned*>(&hi));
    *reinterpret_cast<uint2*>(s + row*64 + ((chunk ^ (row & 7)) << 3) + half*4) = v;
}

// ---------------- W_lin fp32 -> f16 prepass ----------------
__global__ __launch_bounds__(256) void wconv_kernel(const float* __restrict__ W){
    int i = (blockIdx.x*256 + threadIdx.x)*4;
    float4 v = *(const float4*)(W + i);
    __half2 lo = __floats2half2_rn(v.x, v.y);
    __half2 hi = __floats2half2_rn(v.z, v.w);
    *(uint2*)(g_wl + i) = make_uint2(*reinterpret_cast<unsigned*>(&lo), *reinterpret_cast<unsigned*>(&hi));
}

// ---------------- Q projection: q = (x @ Wq^T) * 0.125 * log2(e), f16 out -------
__global__ __launch_bounds__(256) void qproj_kernel(const float* __restrict__ x,
                                                    const float* __restrict__ Wq){
    __shared__ bf16 sX[128*64];
    __shared__ bf16 sW[64*64];
    const int t = threadIdx.x, lane = t & 31, w = t >> 5;
    const int rbase = blockIdx.x * 128;
#pragma unroll
    for (int it = 0; it < 8; it++){
        int idx = it*256 + t, row = idx >> 4, c4 = idx & 15;
        st_sw4(sX, row, c4, *(const float4*)(x + (size_t)(rbase+row)*64 + c4*4));
    }
#pragma unroll
    for (int it = 0; it < 4; it++){
        int idx = it*256 + t, row = idx >> 4, c4 = idx & 15;
        st_sw4(sW, row, c4, *(const float4*)(Wq + row*64 + c4*4));
    }
    __syncthreads();
    float acc[8][4] = {};
    const int rA  = w*16 + (lane & 7) + (lane & 8);
    const int rB0 = (lane & 7) + ((lane & 16) >> 1);
#pragma unroll
    for (int kk = 0; kk < 4; kk++){
        unsigned af[4];
        int cA = 2*kk + (lane >> 4);
        ldsm4(sptr(sX + rA*64 + ((cA ^ (rA & 7)) << 3)), af[0], af[1], af[2], af[3]);
        int cB = 2*kk + ((lane >> 3) & 1);
#pragma unroll
        for (int jp = 0; jp < 4; jp++){
            int r = jp*16 + rB0;
            unsigned b0, b1, b2, b3;
            ldsm4(sptr(sW + r*64 + ((cB ^ (r & 7)) << 3)), b0, b1, b2, b3);
            mma_bf16(acc[2*jp],   af, b0, b1);
            mma_bf16(acc[2*jp+1], af, b2, b3);
        }
    }
    const float qs = 0.125f * LOG2E;
    const int g = lane >> 2, cc = (lane & 3)*2;
#pragma unroll
    for (int j = 0; j < 8; j++){
        size_t r0 = (size_t)(rbase + w*16 + g)*64 + j*8 + cc;
        *(__half2*)(g_q + r0)       = __floats2half2_rn(acc[j][0]*qs, acc[j][1]*qs);
        *(__half2*)(g_q + r0 + 512) = __floats2half2_rn(acc[j][2]*qs, acc[j][3]*qs);
    }
}

// ---------------- K/V projection (mma), f16 out ----------------
__global__ __launch_bounds__(256) void kvproj_kernel(const float* __restrict__ x,
                                                     const float* __restrict__ Wk,
                                                     const float* __restrict__ Wv){
    __shared__ bf16 sX [128*64];
    __shared__ bf16 sWk[64*64];
    __shared__ bf16 sWv[64*64];
    const int t = threadIdx.x, lane = t & 31, w = t >> 5;
    const int rbase = blockIdx.x * 128;
#pragma unroll
    for (int it = 0; it < 8; it++){
        int idx = it*256 + t, row = idx >> 4, c4 = idx & 15;
        st_sw4(sX, row, c4, *(const float4*)(x + (size_t)(rbase+row)*64 + c4*4));
    }
#pragma unroll
    for (int it = 0; it < 4; it++){
        int idx = it*256 + t, row = idx >> 4, c4 = idx & 15;
        st_sw4(sWk, row, c4, *(const float4*)(Wk + row*64 + c4*4));
        st_sw4(sWv, row, c4, *(const float4*)(Wv + row*64 + c4*4));
    }
    __syncthreads();
    float ak[8][4] = {}, av[8][4] = {};
    const int rA  = w*16 + (lane & 7) + (lane & 8);
    const int rB0 = (lane & 7) + ((lane & 16) >> 1);
#pragma unroll
    for (int kk = 0; kk < 4; kk++){
        unsigned af[4];
        int cA = 2*kk + (lane >> 4);
        ldsm4(sptr(sX + rA*64 + ((cA ^ (rA & 7)) << 3)), af[0], af[1], af[2], af[3]);
        int cB = 2*kk + ((lane >> 3) & 1);
#pragma unroll
        for (int jp = 0; jp < 4; jp++){
            int r = jp*16 + rB0;
            unsigned b0, b1, b2, b3;
            ldsm4(sptr(sWk + r*64 + ((cB ^ (r & 7)) << 3)), b0, b1, b2, b3);
            mma_bf16(ak[2*jp],   af, b0, b1);
            mma_bf16(ak[2*jp+1], af, b2, b3);
            ldsm4(sptr(sWv + r*64 + ((cB ^ (r & 7)) << 3)), b0, b1, b2, b3);
            mma_bf16(av[2*jp],   af, b0, b1);
            mma_bf16(av[2*jp+1], af, b2, b3);
        }
    }
    const int g = lane >> 2, cc = (lane & 3)*2;
#pragma unroll
    for (int j = 0; j < 8; j++){
        size_t r0 = (size_t)(rbase + w*16 + g)*64 + j*8 + cc;
        *(__half2*)(g_k + r0)       = __floats2half2_rn(ak[j][0], ak[j][1]);
        *(__half2*)(g_k + r0 + 512) = __floats2half2_rn(ak[j][2], ak[j][3]);
        *(__half2*)(g_v + r0)       = __floats2half2_rn(av[j][0], av[j][1]);
        *(__half2*)(g_v + r0 + 512) = __floats2half2_rn(av[j][2], av[j][3]);
    }
}

// ---------------- flash attention: 64-row q tiles, 3-stage ring, ILP prefetch ---
// grid (LQ/64, NH, BB), 128 threads = 4 warps x 16 q-rows.
__global__ __launch_bounds__(128, 3) void attn_kernel(const float* __restrict__ kg_mask){
    extern __shared__ char sm[];
    __half* sQ  = (__half*)sm;             // 64x64 = 8KB
    __half* sK  = (__half*)(sm + 8192);    // 3 x 64x64 = 24KB
    __half* sV  = (__half*)(sm + 32768);   // 3 x 64x64 = 24KB
    __half* skb = (__half*)(sm + 57344);   // 2048 halves = 4KB

    const int t = threadIdx.x, lane = t & 31, w = t >> 5;
    const int qt = blockIdx.x, h = blockIdx.y, b = blockIdx.z;

    auto issue = [&](int kt){
        int buf = kt % 3;
        __half* dk = sK + buf*4096;
        __half* dv = sV + buf*4096;
        const __half* gk = g_k + (size_t)(b*LK + kt*64)*HID + h*64;
        const __half* gv = g_v + (size_t)(b*LK + kt*64)*HID + h*64;
#pragma unroll
        for (int it = 0; it < 4; it++){
            int idx = it*128 + t, rr = idx >> 3, c = idx & 7;
            unsigned so = rr*64 + ((c ^ (rr & 7)) << 3);
            cp16(dk + so, gk + (size_t)rr*HID + c*8);
            cp16(dv + so, gv + (size_t)rr*HID + c*8);
        }
        cp_commit();
    };

    issue(0);
    issue(1);

    // mask bias (log2 domain; huge negative saturates exp2 to 0 in f16)
    for (int i = t; i < LK; i += 128)
        skb[i] = __float2half((1.0f - kg_mask[b*LK + i]) * (-30000.0f));
    // Q tile (64 rows)
#pragma unroll
    for (int it = 0; it < 4; it++){
        int idx = it*128 + t, row = idx >> 3, c = idx & 7;
        *(uint4*)(sQ + row*64 + ((c ^ (row & 7)) << 3)) =
            *(const uint4*)(g_q + (size_t)(b*LQ + qt*64 + row)*HID + h*64 + c*8);
    }
    __syncthreads();

    // resident Q fragments: 4 k-chunks (16 rows per warp)
    unsigned qf[4][4];
    {
        int r = w*16 + (lane & 7) + (lane & 8);
#pragma unroll
        for (int kk = 0; kk < 4; kk++){
            int c = 2*kk + (lane >> 4);
            ldsm4(sptr(sQ + r*64 + ((c ^ (r & 7)) << 3)),
                  qf[kk][0], qf[kk][1], qf[kk][2], qf[kk][3]);
        }
    }

    unsigned O2[8][2] = {};                      // f16x2 accumulators
    unsigned lacc[2] = {};                       // f16x2 row-sums (rows g, g+8)
    const unsigned ONESH = 0x3C003C00u;
    const int rB0 = (lane & 7) + ((lane & 16) >> 1);
    const int rV0 = (lane & 7) + (lane & 8);

    // fragment loaders (double-buffered prefetch)
    auto ldK = [&](__half* K, int kk, unsigned f[4][4]){
        int cB = 2*kk + ((lane >> 3) & 1);
#pragma unroll
        for (int jp = 0; jp < 4; jp++){
            int r = jp*16 + rB0;
            ldsm4(sptr(K + r*64 + ((cB ^ (r & 7)) << 3)), f[jp][0], f[jp][1], f[jp][2], f[jp][3]);
        }
    };
    auto ldV = [&](__half* V, int kk2, unsigned f[4][4]){
        int r = kk2*16 + rV0;
#pragma unroll
        for (int jp = 0; jp < 4; jp++){
            int c = 2*jp + (lane >> 4);
            ldsm4t(sptr(V + r*64 + ((c ^ (r & 7)) << 3)), f[jp][0], f[jp][1], f[jp][2], f[jp][3]);
        }
    };

    for (int kt = 0; kt < NT; kt++){
        cp_wait1();
        __syncthreads();
        // prefetch tile kt+2 into ring slot (kt+2)%3 == (kt-1)%3, freed by the barrier above
        if (kt + 2 < NT) issue(kt + 2);
        else cp_commit();
        __half* K = sK + (kt % 3)*4096;
        __half* V = sV + (kt % 3)*4096;

        // ---- S = Q K^T (f16 accum), 64 keys, K-fragment prefetch ----
        unsigned kfA[4][4], kfB[4][4];
        ldK(K, 0, kfA);
        unsigned S2[8][2] = {};
#pragma unroll
        for (int kk = 0; kk < 4; kk++){
            unsigned (*cur)[4] = (kk & 1) ? kfB : kfA;
            if (kk < 3) ldK(K, kk + 1, (kk & 1) ? kfA : kfB);
#pragma unroll
            for (int jp = 0; jp < 4; jp++){
                mma_f16c(S2[2*jp],   qf[kk], cur[jp][0], cur[jp][1]);
                mma_f16c(S2[2*jp+1], qf[kk], cur[jp][2], cur[jp][3]);
            }
        }

        // prefetch first V fragments before exp (hides exp latency under LDS)
        unsigned vfA[4][4], vfB[4][4];
        ldV(V, 0, vfA);

        // ---- p = 2^(S + bias), in place ----
        const __half2* kb2 = (const __half2*)(skb + kt*64);
#pragma unroll
        for (int j = 0; j < 8; j++){
            __half2 bias = kb2[j*4 + (lane & 3)];
            __half2 s0 = *(__half2*)&S2[j][0];
            __half2 s1 = *(__half2*)&S2[j][1];
            s0 = h2exp2(__hadd2(s0, bias));
            s1 = h2exp2(__hadd2(s1, bias));
            S2[j][0] = *(unsigned*)&s0;
            S2[j][1] = *(unsigned*)&s1;
        }

        // ---- O += P V ; l += P @ ones, V-fragment prefetch ----
#pragma unroll
        for (int kk2 = 0; kk2 < 4; kk2++){
            unsigned (*cur)[4] = (kk2 & 1) ? vfB : vfA;
            if (kk2 < 3) ldV(V, kk2 + 1, (kk2 & 1) ? vfA : vfB);
            mma_f16c(lacc, &S2[2*kk2][0], ONESH, ONESH);
#pragma unroll
            for (int jp = 0; jp < 4; jp++){
                mma_f16c(O2[2*jp],   &S2[2*kk2][0], cur[jp][0], cur[jp][1]);
                mma_f16c(O2[2*jp+1], &S2[2*kk2][0], cur[jp][2], cur[jp][3]);
            }
        }
    }

    // epilogue: normalize by row sums (f32 divide), store ctx f16
    const int g = lane >> 2, cc = (lane & 3)*2;
    float l0 = __low2float(*(__half2*)&lacc[0]);    // row g
    float l1 = __low2float(*(__half2*)&lacc[1]);    // row g+8
    float inv0 = 1.0f / l0, inv1 = 1.0f / l1;
#pragma unroll
    for (int j = 0; j < 8; j++){
        float2 a = __half22float2(*(__half2*)&O2[j][0]);
        float2 c = __half22float2(*(__half2*)&O2[j][1]);
        size_t r0 = (size_t)(b*LQ + qt*64 + w*16 + g)*HID + h*64 + j*8 + cc;
        *(__half2*)(g_ctx + r0)         = __floats2half2_rn(a.x*inv0, a.y*inv0);
        *(__half2*)(g_ctx + r0 + 8*HID) = __floats2half2_rn(c.x*inv1, c.y*inv1);
    }
}

// ---------------- output linear + gelu + residual (fused epilogue) --------------
__global__ __launch_bounds__(256) void lin_kernel(const float* __restrict__ bias,
                                                  const float* __restrict__ resid){
    extern __shared__ char sm[];
    __half* sA = (__half*)sm;            // 2 x 128x64 = 32KB
    __half* sW = (__half*)(sm + 32768);  // 2 x 128x64 = 32KB
    const int t = threadIdx.x, lane = t & 31, w = t >> 5;
    const int ct = blockIdx.x, rt = blockIdx.y;
    const int wrow = (w >> 1)*32, wcol = (w & 1)*64;

    auto issue = [&](int ki, int buf){
        __half* da = sA + buf*8192;
        __half* dw = sW + buf*8192;
#pragma unroll
        for (int it = 0; it < 4; it++){
            int idx = it*256 + t, row = idx >> 3, c = idx & 7;
            unsigned so = row*64 + ((c ^ (row & 7)) << 3);
            cp16(da + so, g_ctx + (size_t)(rt*128 + row)*HID + ki*64 + c*8);
            cp16(dw + so, g_wl  + (size_t)(ct*128 + row)*HID + ki*64 + c*8);
        }
        cp_commit();
    };

    issue(0, 0);
    issue(1, 1);

    unsigned acc2[2][8][2] = {};
    const int rB0 = (lane & 7) + ((lane & 16) >> 1);

    for (int ki = 0; ki < HID/64; ki++){
        cp_wait1();
        __syncthreads();
        __half* A  = sA + (ki & 1)*8192;
        __half* Wt = sW + (ki & 1)*8192;
#pragma unroll
        for (int kk = 0; kk < 4; kk++){
            unsigned af0[4], af1[4];
            int cA = 2*kk + (lane >> 4);
            int rA0 = wrow + (lane & 7) + (lane & 8);
            int rA1 = rA0 + 16;
            ldsm4(sptr(A + rA0*64 + ((cA ^ (rA0 & 7)) << 3)), af0[0], af0[1], af0[2], af0[3]);
            ldsm4(sptr(A + rA1*64 + ((cA ^ (rA1 & 7)) << 3)), af1[0], af1[1], af1[2], af1[3]);
            int cB = 2*kk + ((lane >> 3) & 1);
#pragma unroll
            for (int jp = 0; jp < 4; jp++){
                int r = wcol + jp*16 + rB0;
                unsigned b0, b1, b2, b3;
                ldsm4(sptr(Wt + r*64 + ((cB ^ (r & 7)) << 3)), b0, b1, b2, b3);
                mma_f16c(acc2[0][2*jp],   af0, b0, b1);
                mma_f16c(acc2[0][2*jp+1], af0, b2, b3);
                mma_f16c(acc2[1][2*jp],   af1, b0, b1);
                mma_f16c(acc2[1][2*jp+1], af1, b2, b3);
            }
        }
        __syncthreads();
        if (ki + 2 < HID/64) issue(ki + 2, ki & 1);
        else cp_commit();
    }

    // epilogue: x = gelu(lin + bias) + resid  (fused; final kernel does LN only)
    const int g = lane >> 2, cc = (lane & 3)*2;
#pragma unroll
    for (int rg = 0; rg < 2; rg++){
#pragma unroll
        for (int j = 0; j < 8; j++){
            int col = ct*128 + wcol + j*8 + cc;
            float2 bv = *(const float2*)(bias + col);
            float2 a = __half22float2(*(__half2*)&acc2[rg][j][0]);
            float2 c = __half22float2(*(__half2*)&acc2[rg][j][1]);
            size_t row0 = (size_t)(rt*128 + wrow + rg*16 + g);
            float v0 = a.x + bv.x, v1 = a.y + bv.y;
            float v2 = c.x + bv.x, v3 = c.y + bv.y;
            float2 rs0 = *(const float2*)(resid + row0*HID + col);
            float2 rs1 = *(const float2*)(resid + (row0 + 8)*HID + col);
            float g0 = 0.5f*v0*(1.0f + erff(v0*0.70710678f)) + rs0.x;
            float g1 = 0.5f*v1*(1.0f + erff(v1*0.70710678f)) + rs0.y;
            float g2 = 0.5f*v2*(1.0f + erff(v2*0.70710678f)) + rs1.x;
            float g3 = 0.5f*v3*(1.0f + erff(v3*0.70710678f)) + rs1.y;
            *(float2*)(g_lin + row0*HID + col)       = make_float2(g0, g1);
            *(float2*)(g_lin + (row0 + 8)*HID + col) = make_float2(g2, g3);
        }
    }
}

// ---------------- layernorm only ----------------
__global__ __launch_bounds__(256) void final_kernel(const float* __restrict__ gamma,
                                                    const float* __restrict__ beta,
                                                    float* __restrict__ out){
    __shared__ float red1[8];
    __shared__ float red2[8];
    const int t = threadIdx.x;
    const size_t tok = blockIdx.x;

    float xv[4];
#pragma unroll
    for (int i = 0; i < 4; i++)
        xv[i] = g_lin[tok*HID + t + i*256];
    float s = xv[0] + xv[1] + xv[2] + xv[3];
#pragma unroll
    for (int off = 16; off; off >>= 1) s += __shfl_xor_sync(0xffffffffu, s, off);
    if ((t & 31) == 0) red1[t >> 5] = s;
    __syncthreads();
    float mu = (red1[0]+red1[1]+red1[2]+red1[3]+red1[4]+red1[5]+red1[6]+red1[7]) * (1.0f/HID);
    float v2 = 0.f;
#pragma unroll
    for (int i = 0; i < 4; i++){ float d = xv[i] - mu; v2 += d*d; }
#pragma unroll
    for (int off = 16; off; off >>= 1) v2 += __shfl_xor_sync(0xffffffffu, v2, off);
    if ((t & 31) == 0) red2[t >> 5] = v2;
    __syncthreads();
    float var = (red2[0]+red2[1]+red2[2]+red2[3]+red2[4]+red2[5]+red2[6]+red2[7]) * (1.0f/HID);
    float rstd = rsqrtf(var + 1e-5f);
#pragma unroll
    for (int i = 0; i < 4; i++){
        int c = t + i*256;
        out[tok*HID + c] = (xv[i] - mu) * rstd * gamma[c] + beta[c];
    }
}

// ---------------- launch --------------------------------------------------------
extern "C" void kernel_launch(void* const* d_in, const int* in_sizes, int n_in,
                              void* d_out, int out_size) {
    const float* input_embed = (const float*)d_in[0];
    const float* kg_embed    = (const float*)d_in[1];
    // d_in[2] input_mask: per-row constant additive shift -> softmax-invariant, unused
    const float* kg_mask     = (const float*)d_in[3];
    const float* Wq          = (const float*)d_in[4];
    const float* Wk          = (const float*)d_in[5];
    const float* Wv          = (const float*)d_in[6];
    const float* W_lin       = (const float*)d_in[7];
    const float* b_lin       = (const float*)d_in[8];
    const float* ln_gamma    = (const float*)d_in[9];
    const float* ln_beta     = (const float*)d_in[10];
    float* out = (float*)d_out;

    const int attn_smem = 61440;  // 60KB -> 3 CTAs/SM
    const int lin_smem  = 65536;
    cudaFuncSetAttribute(attn_kernel, cudaFuncAttributeMaxDynamicSharedMemorySize, attn_smem);
    cudaFuncSetAttribute(lin_kernel,  cudaFuncAttributeMaxDynamicSharedMemorySize, lin_smem);
    cudaFuncSetAttribute(attn_kernel, cudaFuncAttributePreferredSharedMemoryCarveout, 100);
    cudaFuncSetAttribute(lin_kernel,  cudaFuncAttributePreferredSharedMemoryCarveout, 100);

    wconv_kernel <<<HID*HID/1024, 256>>>(W_lin);
    qproj_kernel <<<(BB*LQ*NH)/128, 256>>>(input_embed, Wq);
    kvproj_kernel<<<(BB*LK*NH)/128, 256>>>(kg_embed, Wk, Wv);
    attn_kernel  <<<dim3(LQ/64, NH, BB), 128, attn_smem>>>(kg_mask);
    lin_kernel   <<<dim3(HID/128, (BB*LQ)/128), 256, lin_smem>>>(b_lin, input_embed);
    final_kernel <<<BB*LQ, 256>>>(ln_gamma, ln_beta, out);
}

// round 14
// speedup vs baseline: 1.0446x; 1.0038x over previous
#include <cuda_runtime.h>
#include <cuda_bf16.h>
#include <cuda_fp16.h>
#include <cstdint>
#include <math.h>

#define BB 8
#define LQ 512
#define LK 2048
#define NH 16
#define HID 1024
#define NT (LK/64)   // 32 key tiles

using bf16  = __nv_bfloat16;
using bf162 = __nv_bfloat162;

#define LOG2E 1.4426950408889634f

// ---------------- scratch ----------------
__device__ __half g_q  [BB*LQ*HID];
__device__ __half g_k  [BB*LK*HID];
__device__ __half g_v  [BB*LK*HID];
__device__ __half g_ctx[BB*LQ*HID];
__device__ __half g_wl [HID*HID];
__device__ float  g_lin[BB*LQ*HID];

// ---------------- helpers ----------------
__device__ __forceinline__ unsigned sptr(const void* p){
    return (unsigned)__cvta_generic_to_shared(p);
}
__device__ __forceinline__ void ldsm4(unsigned a, unsigned& r0, unsigned& r1, unsigned& r2, unsigned& r3){
    asm volatile("ldmatrix.sync.aligned.m8n8.x4.shared.b16 {%0,%1,%2,%3},[%4];"
                 : "=r"(r0),"=r"(r1),"=r"(r2),"=r"(r3) : "r"(a));
}
__device__ __forceinline__ void ldsm4t(unsigned a, unsigned& r0, unsigned& r1, unsigned& r2, unsigned& r3){
    asm volatile("ldmatrix.sync.aligned.m8n8.x4.trans.shared.b16 {%0,%1,%2,%3},[%4];"
                 : "=r"(r0),"=r"(r1),"=r"(r2),"=r"(r3) : "r"(a));
}
__device__ __forceinline__ void mma_bf16(float* c, const unsigned* a, unsigned b0, unsigned b1){
    asm volatile("mma.sync.aligned.m16n8k16.row.col.f32.bf16.bf16.f32 "
                 "{%0,%1,%2,%3},{%4,%5,%6,%7},{%8,%9},{%0,%1,%2,%3};"
                 : "+f"(c[0]),"+f"(c[1]),"+f"(c[2]),"+f"(c[3])
                 : "r"(a[0]),"r"(a[1]),"r"(a[2]),"r"(a[3]),"r"(b0),"r"(b1));
}
// f16 operands, f16 accumulators (2 regs, packed f16x2)
__device__ __forceinline__ void mma_f16c(unsigned* d, const unsigned* a, unsigned b0, unsigned b1){
    asm volatile("mma.sync.aligned.m16n8k16.row.col.f16.f16.f16.f16 "
                 "{%0,%1},{%2,%3,%4,%5},{%6,%7},{%0,%1};"
                 : "+r"(d[0]),"+r"(d[1])
                 : "r"(a[0]),"r"(a[1]),"r"(a[2]),"r"(a[3]),"r"(b0),"r"(b1));
}
__device__ __forceinline__ void cp16(void* dst, const void* src){
    asm volatile("cp.async.cg.shared.global [%0],[%1],16;" :: "r"(sptr(dst)),"l"(src));
}
__device__ __forceinline__ void cp_commit(){ asm volatile("cp.async.commit_group;"); }
__device__ __forceinline__ void cp_wait1(){ asm volatile("cp.async.wait_group 1;"); }
__device__ __forceinline__ void st_sw4(bf16* s, int row, int c4, float4 f){
    bf162 lo = __floats2bfloat162_rn(f.x, f.y);
    bf162 hi = __floats2bfloat162_rn(f.z, f.w);
    int chunk = c4 >> 1, half = c4 & 1;
    uint2 v = make_uint2(*reinterpret_cast<unsigned*>(&lo), *reinterpret_cast<unsigned*>(&hi));
    *reinterpret_cast<uint2*>(s + row*64 + ((chunk ^ (row & 7)) << 3) + half*4) = v;
}

// ---------------- W_lin fp32 -> f16 prepass ----------------
__global__ __launch_bounds__(256) void wconv_kernel(const float* __restrict__ W){
    int i = (blockIdx.x*256 + threadIdx.x)*4;
    float4 v = *(const float4*)(W + i);
    __half2 lo = __floats2half2_rn(v.x, v.y);
    __half2 hi = __floats2half2_rn(v.z, v.w);
    *(uint2*)(g_wl + i) = make_uint2(*reinterpret_cast<unsigned*>(&lo), *reinterpret_cast<unsigned*>(&hi));
}

// ---------------- Q projection: q = (x @ Wq^T) * 0.125 * log2(e), f16 out -------
__global__ __launch_bounds__(256) void qproj_kernel(const float* __restrict__ x,
                                                    const float* __restrict__ Wq){
    __shared__ bf16 sX[128*64];
    __shared__ bf16 sW[64*64];
    const int t = threadIdx.x, lane = t & 31, w = t >> 5;
    const int rbase = blockIdx.x * 128;
#pragma unroll
    for (int it = 0; it < 8; it++){
        int idx = it*256 + t, row = idx >> 4, c4 = idx & 15;
        st_sw4(sX, row, c4, *(const float4*)(x + (size_t)(rbase+row)*64 + c4*4));
    }
#pragma unroll
    for (int it = 0; it < 4; it++){
        int idx = it*256 + t, row = idx >> 4, c4 = idx & 15;
        st_sw4(sW, row, c4, *(const float4*)(Wq + row*64 + c4*4));
    }
    __syncthreads();
    float acc[8][4] = {};
    const int rA  = w*16 + (lane & 7) + (lane & 8);
    const int rB0 = (lane & 7) + ((lane & 16) >> 1);
#pragma unroll
    for (int kk = 0; kk < 4; kk++){
        unsigned af[4];
        int cA = 2*kk + (lane >> 4);
        ldsm4(sptr(sX + rA*64 + ((cA ^ (rA & 7)) << 3)), af[0], af[1], af[2], af[3]);
        int cB = 2*kk + ((lane >> 3) & 1);
#pragma unroll
        for (int jp = 0; jp < 4; jp++){
            int r = jp*16 + rB0;
            unsigned b0, b1, b2, b3;
            ldsm4(sptr(sW + r*64 + ((cB ^ (r & 7)) << 3)), b0, b1, b2, b3);
            mma_bf16(acc[2*jp],   af, b0, b1);
            mma_bf16(acc[2*jp+1], af, b2, b3);
        }
    }
    const float qs = 0.125f * LOG2E;
    const int g = lane >> 2, cc = (lane & 3)*2;
#pragma unroll
    for (int j = 0; j < 8; j++){
        size_t r0 = (size_t)(rbase + w*16 + g)*64 + j*8 + cc;
        *(__half2*)(g_q + r0)       = __floats2half2_rn(acc[j][0]*qs, acc[j][1]*qs);
        *(__half2*)(g_q + r0 + 512) = __floats2half2_rn(acc[j][2]*qs, acc[j][3]*qs);
    }
}

// ---------------- K/V projection (mma), f16 out ----------------
__global__ __launch_bounds__(256) void kvproj_kernel(const float* __restrict__ x,
                                                     const float* __restrict__ Wk,
                                                     const float* __restrict__ Wv){
    __shared__ bf16 sX [128*64];
    __shared__ bf16 sWk[64*64];
    __shared__ bf16 sWv[64*64];
    const int t = threadIdx.x, lane = t & 31, w = t >> 5;
    const int rbase = blockIdx.x * 128;
#pragma unroll
    for (int it = 0; it < 8; it++){
        int idx = it*256 + t, row = idx >> 4, c4 = idx & 15;
        st_sw4(sX, row, c4, *(const float4*)(x + (size_t)(rbase+row)*64 + c4*4));
    }
#pragma unroll
    for (int it = 0; it < 4; it++){
        int idx = it*256 + t, row = idx >> 4, c4 = idx & 15;
        st_sw4(sWk, row, c4, *(const float4*)(Wk + row*64 + c4*4));
        st_sw4(sWv, row, c4, *(const float4*)(Wv + row*64 + c4*4));
    }
    __syncthreads();
    float ak[8][4] = {}, av[8][4] = {};
    const int rA  = w*16 + (lane & 7) + (lane & 8);
    const int rB0 = (lane & 7) + ((lane & 16) >> 1);
#pragma unroll
    for (int kk = 0; kk < 4; kk++){
        unsigned af[4];
        int cA = 2*kk + (lane >> 4);
        ldsm4(sptr(sX + rA*64 + ((cA ^ (rA & 7)) << 3)), af[0], af[1], af[2], af[3]);
        int cB = 2*kk + ((lane >> 3) & 1);
#pragma unroll
        for (int jp = 0; jp < 4; jp++){
            int r = jp*16 + rB0;
            unsigned b0, b1, b2, b3;
            ldsm4(sptr(sWk + r*64 + ((cB ^ (r & 7)) << 3)), b0, b1, b2, b3);
            mma_bf16(ak[2*jp],   af, b0, b1);
            mma_bf16(ak[2*jp+1], af, b2, b3);
            ldsm4(sptr(sWv + r*64 + ((cB ^ (r & 7)) << 3)), b0, b1, b2, b3);
            mma_bf16(av[2*jp],   af, b0, b1);
            mma_bf16(av[2*jp+1], af, b2, b3);
        }
    }
    const int g = lane >> 2, cc = (lane & 3)*2;
#pragma unroll
    for (int j = 0; j < 8; j++){
        size_t r0 = (size_t)(rbase + w*16 + g)*64 + j*8 + cc;
        *(__half2*)(g_k + r0)       = __floats2half2_rn(ak[j][0], ak[j][1]);
        *(__half2*)(g_k + r0 + 512) = __floats2half2_rn(ak[j][2], ak[j][3]);
        *(__half2*)(g_v + r0)       = __floats2half2_rn(av[j][0], av[j][1]);
        *(__half2*)(g_v + r0 + 512) = __floats2half2_rn(av[j][2], av[j][3]);
    }
}

// ---------------- flash attention: 128-row q tiles, 3-ring, ILP prefetch --------
// grid (LQ/128, NH, BB), 128 threads = 4 warps x 32 q-rows (2 rowgroups).
__global__ __launch_bounds__(128, 3) void attn_kernel(const float* __restrict__ kg_mask){
    extern __shared__ char sm[];
    __half* sQ  = (__half*)sm;             // 128x64 = 16KB
    __half* sK  = (__half*)(sm + 16384);   // 3 x 64x64 = 24KB
    __half* sV  = (__half*)(sm + 40960);   // 3 x 64x64 = 24KB
    __half* skb = (__half*)(sm + 65536);   // 2048 halves = 4KB

    const int t = threadIdx.x, lane = t & 31, w = t >> 5;
    const int qt = blockIdx.x, h = blockIdx.y, b = blockIdx.z;

    auto issue = [&](int kt){
        int buf = kt % 3;
        __half* dk = sK + buf*4096;
        __half* dv = sV + buf*4096;
        const __half* gk = g_k + (size_t)(b*LK + kt*64)*HID + h*64;
        const __half* gv = g_v + (size_t)(b*LK + kt*64)*HID + h*64;
#pragma unroll
        for (int it = 0; it < 4; it++){
            int idx = it*128 + t, rr = idx >> 3, c = idx & 7;
            unsigned so = rr*64 + ((c ^ (rr & 7)) << 3);
            cp16(dk + so, gk + (size_t)rr*HID + c*8);
            cp16(dv + so, gv + (size_t)rr*HID + c*8);
        }
        cp_commit();
    };

    issue(0);
    issue(1);

    // mask bias (log2 domain; huge negative saturates exp2 to 0 in f16)
    for (int i = t; i < LK; i += 128)
        skb[i] = __float2half((1.0f - kg_mask[b*LK + i]) * (-30000.0f));
    // Q tile (128 rows)
#pragma unroll
    for (int it = 0; it < 8; it++){
        int idx = it*128 + t, row = idx >> 3, c = idx & 7;
        *(uint4*)(sQ + row*64 + ((c ^ (row & 7)) << 3)) =
            *(const uint4*)(g_q + (size_t)(b*LQ + qt*128 + row)*HID + h*64 + c*8);
    }
    __syncthreads();

    // resident Q fragments: 2 rowgroups x 4 k-chunks
    unsigned qf[2][4][4];
#pragma unroll
    for (int rg = 0; rg < 2; rg++){
        int r = w*32 + rg*16 + (lane & 7) + (lane & 8);
#pragma unroll
        for (int kk = 0; kk < 4; kk++){
            int c = 2*kk + (lane >> 4);
            ldsm4(sptr(sQ + r*64 + ((c ^ (r & 7)) << 3)),
                  qf[rg][kk][0], qf[rg][kk][1], qf[rg][kk][2], qf[rg][kk][3]);
        }
    }

    unsigned O2[2][8][2] = {};                   // f16x2 accumulators
    __half2 lh[2][2] = {{__floats2half2_rn(0,0),__floats2half2_rn(0,0)},
                        {__floats2half2_rn(0,0),__floats2half2_rn(0,0)}};  // per-thread l partials
    const int rB0 = (lane & 7) + ((lane & 16) >> 1);
    const int rV0 = (lane & 7) + (lane & 8);

    // fragment loaders (double-buffered prefetch); 32-key half hk
    auto ldK = [&](__half* K, int hk, int kk, unsigned f[2][4]){
        int cB = 2*kk + ((lane >> 3) & 1);
#pragma unroll
        for (int jp = 0; jp < 2; jp++){
            int r = hk*32 + jp*16 + rB0;
            ldsm4(sptr(K + r*64 + ((cB ^ (r & 7)) << 3)), f[jp][0], f[jp][1], f[jp][2], f[jp][3]);
        }
    };
    auto ldV = [&](__half* V, int hk, int kk2, unsigned f[4][4]){
        int r = hk*32 + kk2*16 + rV0;
#pragma unroll
        for (int jp = 0; jp < 4; jp++){
            int c = 2*jp + (lane >> 4);
            ldsm4t(sptr(V + r*64 + ((c ^ (r & 7)) << 3)), f[jp][0], f[jp][1], f[jp][2], f[jp][3]);
        }
    };

    for (int kt = 0; kt < NT; kt++){
        cp_wait1();
        __syncthreads();
        if (kt + 2 < NT) issue(kt + 2);
        else cp_commit();
        __half* K = sK + (kt % 3)*4096;
        __half* V = sV + (kt % 3)*4096;

#pragma unroll
        for (int hk = 0; hk < 2; hk++){
            // ---- S = Q K^T (f16 accum), 32 keys, K-fragment prefetch ----
            unsigned kfA[2][4], kfB[2][4];
            ldK(K, hk, 0, kfA);
            unsigned S2[2][4][2] = {};
#pragma unroll
            for (int kk = 0; kk < 4; kk++){
                unsigned (*cur)[4] = (kk & 1) ? kfB : kfA;
                if (kk < 3) ldK(K, hk, kk + 1, (kk & 1) ? kfA : kfB);
#pragma unroll
                for (int jp = 0; jp < 2; jp++){
                    mma_f16c(S2[0][2*jp],   qf[0][kk], cur[jp][0], cur[jp][1]);
                    mma_f16c(S2[0][2*jp+1], qf[0][kk], cur[jp][2], cur[jp][3]);
                    mma_f16c(S2[1][2*jp],   qf[1][kk], cur[jp][0], cur[jp][1]);
                    mma_f16c(S2[1][2*jp+1], qf[1][kk], cur[jp][2], cur[jp][3]);
                }
            }

            // prefetch first V fragments before exp (hides exp under LDS latency)
            unsigned vfA[4][4], vfB[4][4];
            ldV(V, hk, 0, vfA);

            // ---- p = 2^(S + bias) in place; accumulate l partials (no MMA) ----
            const __half2* kb2 = (const __half2*)(skb + kt*64 + hk*32);
#pragma unroll
            for (int rg = 0; rg < 2; rg++){
#pragma unroll
                for (int j = 0; j < 4; j++){
                    __half2 bias = kb2[j*4 + (lane & 3)];
                    __half2 s0 = h2exp2(__hadd2(*(__half2*)&S2[rg][j][0], bias));
                    __half2 s1 = h2exp2(__hadd2(*(__half2*)&S2[rg][j][1], bias));
                    lh[rg][0] = __hadd2(lh[rg][0], s0);
                    lh[rg][1] = __hadd2(lh[rg][1], s1);
                    S2[rg][j][0] = *(unsigned*)&s0;
                    S2[rg][j][1] = *(unsigned*)&s1;
                }
            }

            // ---- O += P V, V-fragment prefetch ----
#pragma unroll
            for (int kk2 = 0; kk2 < 2; kk2++){
                unsigned (*cur)[4] = (kk2 & 1) ? vfB : vfA;
                if (kk2 < 1) ldV(V, hk, 1, vfB);
#pragma unroll
                for (int jp = 0; jp < 4; jp++){
                    mma_f16c(O2[0][2*jp],   &S2[0][2*kk2][0], cur[jp][0], cur[jp][1]);
                    mma_f16c(O2[0][2*jp+1], &S2[0][2*kk2][0], cur[jp][2], cur[jp][3]);
                    mma_f16c(O2[1][2*jp],   &S2[1][2*kk2][0], cur[jp][0], cur[jp][1]);
                    mma_f16c(O2[1][2*jp+1], &S2[1][2*kk2][0], cur[jp][2], cur[jp][3]);
                }
            }
        }
    }

    // epilogue: reduce l across the quad (4 lanes share a row), normalize, store
    const int g = lane >> 2, cc = (lane & 3)*2;
#pragma unroll
    for (int rg = 0; rg < 2; rg++){
        float l0 = __low2float(lh[rg][0]) + __high2float(lh[rg][0]);   // row g partial
        float l1 = __low2float(lh[rg][1]) + __high2float(lh[rg][1]);   // row g+8 partial
        l0 += __shfl_xor_sync(0xffffffffu, l0, 1);
        l0 += __shfl_xor_sync(0xffffffffu, l0, 2);
        l1 += __shfl_xor_sync(0xffffffffu, l1, 1);
        l1 += __shfl_xor_sync(0xffffffffu, l1, 2);
        float inv0 = 1.0f / l0, inv1 = 1.0f / l1;
#pragma unroll
        for (int j = 0; j < 8; j++){
            float2 a = __half22float2(*(__half2*)&O2[rg][j][0]);
            float2 c = __half22float2(*(__half2*)&O2[rg][j][1]);
            size_t r0 = (size_t)(b*LQ + qt*128 + w*32 + rg*16 + g)*HID + h*64 + j*8 + cc;
            *(__half2*)(g_ctx + r0)         = __floats2half2_rn(a.x*inv0, a.y*inv0);
            *(__half2*)(g_ctx + r0 + 8*HID) = __floats2half2_rn(c.x*inv1, c.y*inv1);
        }
    }
}

// ---------------- output linear + gelu + residual (fused epilogue) --------------
__global__ __launch_bounds__(256) void lin_kernel(const float* __restrict__ bias,
                                                  const float* __restrict__ resid){
    extern __shared__ char sm[];
    __half* sA = (__half*)sm;            // 2 x 128x64 = 32KB
    __half* sW = (__half*)(sm + 32768);  // 2 x 128x64 = 32KB
    const int t = threadIdx.x, lane = t & 31, w = t >> 5;
    const int ct = blockIdx.x, rt = blockIdx.y;
    const int wrow = (w >> 1)*32, wcol = (w & 1)*64;

    auto issue = [&](int ki, int buf){
        __half* da = sA + buf*8192;
        __half* dw = sW + buf*8192;
#pragma unroll
        for (int it = 0; it < 4; it++){
            int idx = it*256 + t, row = idx >> 3, c = idx & 7;
            unsigned so = row*64 + ((c ^ (row & 7)) << 3);
            cp16(da + so, g_ctx + (size_t)(rt*128 + row)*HID + ki*64 + c*8);
            cp16(dw + so, g_wl  + (size_t)(ct*128 + row)*HID + ki*64 + c*8);
        }
        cp_commit();
    };

    issue(0, 0);
    issue(1, 1);

    unsigned acc2[2][8][2] = {};
    const int rB0 = (lane & 7) + ((lane & 16) >> 1);

    for (int ki = 0; ki < HID/64; ki++){
        cp_wait1();
        __syncthreads();
        __half* A  = sA + (ki & 1)*8192;
        __half* Wt = sW + (ki & 1)*8192;
#pragma unroll
        for (int kk = 0; kk < 4; kk++){
            unsigned af0[4], af1[4];
            int cA = 2*kk + (lane >> 4);
            int rA0 = wrow + (lane & 7) + (lane & 8);
            int rA1 = rA0 + 16;
            ldsm4(sptr(A + rA0*64 + ((cA ^ (rA0 & 7)) << 3)), af0[0], af0[1], af0[2], af0[3]);
            ldsm4(sptr(A + rA1*64 + ((cA ^ (rA1 & 7)) << 3)), af1[0], af1[1], af1[2], af1[3]);
            int cB = 2*kk + ((lane >> 3) & 1);
#pragma unroll
            for (int jp = 0; jp < 4; jp++){
                int r = wcol + jp*16 + rB0;
                unsigned b0, b1, b2, b3;
                ldsm4(sptr(Wt + r*64 + ((cB ^ (r & 7)) << 3)), b0, b1, b2, b3);
                mma_f16c(acc2[0][2*jp],   af0, b0, b1);
                mma_f16c(acc2[0][2*jp+1], af0, b2, b3);
                mma_f16c(acc2[1][2*jp],   af1, b0, b1);
                mma_f16c(acc2[1][2*jp+1], af1, b2, b3);
            }
        }
        __syncthreads();
        if (ki + 2 < HID/64) issue(ki + 2, ki & 1);
        else cp_commit();
    }

    // epilogue: x = gelu(lin + bias) + resid  (final kernel does LN only)
    const int g = lane >> 2, cc = (lane & 3)*2;
#pragma unroll
    for (int rg = 0; rg < 2; rg++){
#pragma unroll
        for (int j = 0; j < 8; j++){
            int col = ct*128 + wcol + j*8 + cc;
            float2 bv = *(const float2*)(bias + col);
            float2 a = __half22float2(*(__half2*)&acc2[rg][j][0]);
            float2 c = __half22float2(*(__half2*)&acc2[rg][j][1]);
            size_t row0 = (size_t)(rt*128 + wrow + rg*16 + g);
            float v0 = a.x + bv.x, v1 = a.y + bv.y;
            float v2 = c.x + bv.x, v3 = c.y + bv.y;
            float2 rs0 = *(const float2*)(resid + row0*HID + col);
            float2 rs1 = *(const float2*)(resid + (row0 + 8)*HID + col);
            float g0 = 0.5f*v0*(1.0f + erff(v0*0.70710678f)) + rs0.x;
            float g1 = 0.5f*v1*(1.0f + erff(v1*0.70710678f)) + rs0.y;
            float g2 = 0.5f*v2*(1.0f + erff(v2*0.70710678f)) + rs1.x;
            float g3 = 0.5f*v3*(1.0f + erff(v3*0.70710678f)) + rs1.y;
            *(float2*)(g_lin + row0*HID + col)       = make_float2(g0, g1);
            *(float2*)(g_lin + (row0 + 8)*HID + col) = make_float2(g2, g3);
        }
    }
}

// ---------------- layernorm only ----------------
__global__ __launch_bounds__(256) void final_kernel(const float* __restrict__ gamma,
                                                    const float* __restrict__ beta,
                                                    float* __restrict__ out){
    __shared__ float red1[8];
    __shared__ float red2[8];
    const int t = threadIdx.x;
    const size_t tok = blockIdx.x;

    float xv[4];
#pragma unroll
    for (int i = 0; i < 4; i++)
        xv[i] = g_lin[tok*HID + t + i*256];
    float s = xv[0] + xv[1] + xv[2] + xv[3];
#pragma unroll
    for (int off = 16; off; off >>= 1) s += __shfl_xor_sync(0xffffffffu, s, off);
    if ((t & 31) == 0) red1[t >> 5] = s;
    __syncthreads();
    float mu = (red1[0]+red1[1]+red1[2]+red1[3]+red1[4]+red1[5]+red1[6]+red1[7]) * (1.0f/HID);
    float v2 = 0.f;
#pragma unroll
    for (int i = 0; i < 4; i++){ float d = xv[i] - mu; v2 += d*d; }
#pragma unroll
    for (int off = 16; off; off >>= 1) v2 += __shfl_xor_sync(0xffffffffu, v2, off);
    if ((t & 31) == 0) red2[t >> 5] = v2;
    __syncthreads();
    float var = (red2[0]+red2[1]+red2[2]+red2[3]+red2[4]+red2[5]+red2[6]+red2[7]) * (1.0f/HID);
    float rstd = rsqrtf(var + 1e-5f);
#pragma unroll
    for (int i = 0; i < 4; i++){
        int c = t + i*256;
        out[tok*HID + c] = (xv[i] - mu) * rstd * gamma[c] + beta[c];
    }
}

// ---------------- launch --------------------------------------------------------
extern "C" void kernel_launch(void* const* d_in, const int* in_sizes, int n_in,
                              void* d_out, int out_size) {
    const float* input_embed = (const float*)d_in[0];
    const float* kg_embed    = (const float*)d_in[1];
    // d_in[2] input_mask: per-row constant additive shift -> softmax-invariant, unused
    const float* kg_mask     = (const float*)d_in[3];
    const float* Wq          = (const float*)d_in[4];
    const float* Wk          = (const float*)d_in[5];
    const float* Wv          = (const float*)d_in[6];
    const float* W_lin       = (const float*)d_in[7];
    const float* b_lin       = (const float*)d_in[8];
    const float* ln_gamma    = (const float*)d_in[9];
    const float* ln_beta     = (const float*)d_in[10];
    float* out = (float*)d_out;

    const int attn_smem = 69632;  // 68KB -> 3 CTAs/SM
    const int lin_smem  = 65536;
    cudaFuncSetAttribute(attn_kernel, cudaFuncAttributeMaxDynamicSharedMemorySize, attn_smem);
    cudaFuncSetAttribute(lin_kernel,  cudaFuncAttributeMaxDynamicSharedMemorySize, lin_smem);
    cudaFuncSetAttribute(attn_kernel, cudaFuncAttributePreferredSharedMemoryCarveout, 100);
    cudaFuncSetAttribute(lin_kernel,  cudaFuncAttributePreferredSharedMemoryCarveout, 100);

    wconv_kernel <<<HID*HID/1024, 256>>>(W_lin);
    qproj_kernel <<<(BB*LQ*NH)/128, 256>>>(input_embed, Wq);
    kvproj_kernel<<<(BB*LK*NH)/128, 256>>>(kg_embed, Wk, Wv);
    attn_kernel  <<<dim3(LQ/128, NH, BB), 128, attn_smem>>>(kg_mask);
    lin_kernel   <<<dim3(HID/128, (BB*LQ)/128), 256, lin_smem>>>(b_lin, input_embed);
    final_kernel <<<BB*LQ, 256>>>(ln_gamma, ln_beta, out);
}

// round 15
// speedup vs baseline: 1.1493x; 1.1003x over previous
#include <cuda_runtime.h>
#include <cuda_bf16.h>
#include <cuda_fp16.h>
#include <cstdint>
#include <math.h>

#define BB 8
#define LQ 512
#define LK 2048
#define NH 16
#define HID 1024
#define NT (LK/64)   // 32 key tiles

using bf16  = __nv_bfloat16;
using bf162 = __nv_bfloat162;

#define LOG2E 1.4426950408889634f

// ---------------- scratch ----------------
__device__ __half g_q  [BB*LQ*HID];
__device__ __half g_k  [BB*LK*HID];
__device__ __half g_v  [BB*LK*HID];
__device__ __half g_ctx[BB*LQ*HID];
__device__ __half g_wl [HID*HID];
__device__ float  g_lin[BB*LQ*HID];

// ---------------- helpers ----------------
__device__ __forceinline__ unsigned sptr(const void* p){
    return (unsigned)__cvta_generic_to_shared(p);
}
__device__ __forceinline__ void ldsm4(unsigned a, unsigned& r0, unsigned& r1, unsigned& r2, unsigned& r3){
    asm volatile("ldmatrix.sync.aligned.m8n8.x4.shared.b16 {%0,%1,%2,%3},[%4];"
                 : "=r"(r0),"=r"(r1),"=r"(r2),"=r"(r3) : "r"(a));
}
__device__ __forceinline__ void ldsm4t(unsigned a, unsigned& r0, unsigned& r1, unsigned& r2, unsigned& r3){
    asm volatile("ldmatrix.sync.aligned.m8n8.x4.trans.shared.b16 {%0,%1,%2,%3},[%4];"
                 : "=r"(r0),"=r"(r1),"=r"(r2),"=r"(r3) : "r"(a));
}
__device__ __forceinline__ void mma_bf16(float* c, const unsigned* a, unsigned b0, unsigned b1){
    asm volatile("mma.sync.aligned.m16n8k16.row.col.f32.bf16.bf16.f32 "
                 "{%0,%1,%2,%3},{%4,%5,%6,%7},{%8,%9},{%0,%1,%2,%3};"
                 : "+f"(c[0]),"+f"(c[1]),"+f"(c[2]),"+f"(c[3])
                 : "r"(a[0]),"r"(a[1]),"r"(a[2]),"r"(a[3]),"r"(b0),"r"(b1));
}
// f16 operands, f16 accumulators (2 regs, packed f16x2)
__device__ __forceinline__ void mma_f16c(unsigned* d, const unsigned* a, unsigned b0, unsigned b1){
    asm volatile("mma.sync.aligned.m16n8k16.row.col.f16.f16.f16.f16 "
                 "{%0,%1},{%2,%3,%4,%5},{%6,%7},{%0,%1};"
                 : "+r"(d[0]),"+r"(d[1])
                 : "r"(a[0]),"r"(a[1]),"r"(a[2]),"r"(a[3]),"r"(b0),"r"(b1));
}
__device__ __forceinline__ void cp16(void* dst, const void* src){
    asm volatile("cp.async.cg.shared.global [%0],[%1],16;" :: "r"(sptr(dst)),"l"(src));
}
__device__ __forceinline__ void cp_commit(){ asm volatile("cp.async.commit_group;"); }
__device__ __forceinline__ void cp_wait1(){ asm volatile("cp.async.wait_group 1;"); }
__device__ __forceinline__ void st_sw4(bf16* s, int row, int c4, float4 f){
    bf162 lo = __floats2bfloat162_rn(f.x, f.y);
    bf162 hi = __floats2bfloat162_rn(f.z, f.w);
    int chunk = c4 >> 1, half = c4 & 1;
    uint2 v = make_uint2(*reinterpret_cast<unsigned*>(&lo), *reinterpret_cast<unsigned*>(&hi));
    *reinterpret_cast<uint2*>(s + row*64 + ((chunk ^ (row & 7)) << 3) + half*4) = v;
}

// ---------------- fused prep: kvproj (0..1023) | qproj (1024..1535) | wconv (1536..2559)
__global__ __launch_bounds__(256) void prep_kernel(const float* __restrict__ xq,
                                                   const float* __restrict__ xkv,
                                                   const float* __restrict__ Wq,
                                                   const float* __restrict__ Wk,
                                                   const float* __restrict__ Wv,
                                                   const float* __restrict__ Wl){
    extern __shared__ char smraw[];
    const int bid = blockIdx.x;
    const int t = threadIdx.x, lane = t & 31, w = t >> 5;

    if (bid < 1024){
        // ---------------- kvproj block ----------------
        bf16* sX  = (bf16*)smraw;             // 128x64 = 16KB
        bf16* sWk = (bf16*)(smraw + 16384);   // 8KB
        bf16* sWv = (bf16*)(smraw + 24576);   // 8KB
        const int rbase = bid * 128;
#pragma unroll
        for (int it = 0; it < 8; it++){
            int idx = it*256 + t, row = idx >> 4, c4 = idx & 15;
            st_sw4(sX, row, c4, *(const float4*)(xkv + (size_t)(rbase+row)*64 + c4*4));
        }
#pragma unroll
        for (int it = 0; it < 4; it++){
            int idx = it*256 + t, row = idx >> 4, c4 = idx & 15;
            st_sw4(sWk, row, c4, *(const float4*)(Wk + row*64 + c4*4));
            st_sw4(sWv, row, c4, *(const float4*)(Wv + row*64 + c4*4));
        }
        __syncthreads();
        float ak[8][4] = {}, av[8][4] = {};
        const int rA  = w*16 + (lane & 7) + (lane & 8);
        const int rB0 = (lane & 7) + ((lane & 16) >> 1);
#pragma unroll
        for (int kk = 0; kk < 4; kk++){
            unsigned af[4];
            int cA = 2*kk + (lane >> 4);
            ldsm4(sptr(sX + rA*64 + ((cA ^ (rA & 7)) << 3)), af[0], af[1], af[2], af[3]);
            int cB = 2*kk + ((lane >> 3) & 1);
#pragma unroll
            for (int jp = 0; jp < 4; jp++){
                int r = jp*16 + rB0;
                unsigned b0, b1, b2, b3;
                ldsm4(sptr(sWk + r*64 + ((cB ^ (r & 7)) << 3)), b0, b1, b2, b3);
                mma_bf16(ak[2*jp],   af, b0, b1);
                mma_bf16(ak[2*jp+1], af, b2, b3);
                ldsm4(sptr(sWv + r*64 + ((cB ^ (r & 7)) << 3)), b0, b1, b2, b3);
                mma_bf16(av[2*jp],   af, b0, b1);
                mma_bf16(av[2*jp+1], af, b2, b3);
            }
        }
        const int g = lane >> 2, cc = (lane & 3)*2;
#pragma unroll
        for (int j = 0; j < 8; j++){
            size_t r0 = (size_t)(rbase + w*16 + g)*64 + j*8 + cc;
            *(__half2*)(g_k + r0)       = __floats2half2_rn(ak[j][0], ak[j][1]);
            *(__half2*)(g_k + r0 + 512) = __floats2half2_rn(ak[j][2], ak[j][3]);
            *(__half2*)(g_v + r0)       = __floats2half2_rn(av[j][0], av[j][1]);
            *(__half2*)(g_v + r0 + 512) = __floats2half2_rn(av[j][2], av[j][3]);
        }
    } else if (bid < 1536){
        // ---------------- qproj block ----------------
        bf16* sX = (bf16*)smraw;              // 16KB
        bf16* sW = (bf16*)(smraw + 16384);    // 8KB
        const int rbase = (bid - 1024) * 128;
#pragma unroll
        for (int it = 0; it < 8; it++){
            int idx = it*256 + t, row = idx >> 4, c4 = idx & 15;
            st_sw4(sX, row, c4, *(const float4*)(xq + (size_t)(rbase+row)*64 + c4*4));
        }
#pragma unroll
        for (int it = 0; it < 4; it++){
            int idx = it*256 + t, row = idx >> 4, c4 = idx & 15;
            st_sw4(sW, row, c4, *(const float4*)(Wq + row*64 + c4*4));
        }
        __syncthreads();
        float acc[8][4] = {};
        const int rA  = w*16 + (lane & 7) + (lane & 8);
        const int rB0 = (lane & 7) + ((lane & 16) >> 1);
#pragma unroll
        for (int kk = 0; kk < 4; kk++){
            unsigned af[4];
            int cA = 2*kk + (lane >> 4);
            ldsm4(sptr(sX + rA*64 + ((cA ^ (rA & 7)) << 3)), af[0], af[1], af[2], af[3]);
            int cB = 2*kk + ((lane >> 3) & 1);
#pragma unroll
            for (int jp = 0; jp < 4; jp++){
                int r = jp*16 + rB0;
                unsigned b0, b1, b2, b3;
                ldsm4(sptr(sW + r*64 + ((cB ^ (r & 7)) << 3)), b0, b1, b2, b3);
                mma_bf16(acc[2*jp],   af, b0, b1);
                mma_bf16(acc[2*jp+1], af, b2, b3);
            }
        }
        const float qs = 0.125f * LOG2E;
        const int g = lane >> 2, cc = (lane & 3)*2;
#pragma unroll
        for (int j = 0; j < 8; j++){
            size_t r0 = (size_t)(rbase + w*16 + g)*64 + j*8 + cc;
            *(__half2*)(g_q + r0)       = __floats2half2_rn(acc[j][0]*qs, acc[j][1]*qs);
            *(__half2*)(g_q + r0 + 512) = __floats2half2_rn(acc[j][2]*qs, acc[j][3]*qs);
        }
    } else {
        // ---------------- wconv block ----------------
        int i = ((bid - 1536)*256 + t)*4;
        float4 v = *(const float4*)(Wl + i);
        __half2 lo = __floats2half2_rn(v.x, v.y);
        __half2 hi = __floats2half2_rn(v.z, v.w);
        *(uint2*)(g_wl + i) = make_uint2(*reinterpret_cast<unsigned*>(&lo), *reinterpret_cast<unsigned*>(&hi));
    }
}

// ---------------- flash attention: 128-row q tiles, 3-ring, ILP prefetch --------
// grid (LQ/128, NH, BB), 128 threads = 4 warps x 32 q-rows (2 rowgroups).
__global__ __launch_bounds__(128, 3) void attn_kernel(const float* __restrict__ kg_mask){
    extern __shared__ char sm[];
    __half* sQ  = (__half*)sm;             // 128x64 = 16KB
    __half* sK  = (__half*)(sm + 16384);   // 3 x 64x64 = 24KB
    __half* sV  = (__half*)(sm + 40960);   // 3 x 64x64 = 24KB
    __half* skb = (__half*)(sm + 65536);   // 2048 halves = 4KB

    const int t = threadIdx.x, lane = t & 31, w = t >> 5;
    const int qt = blockIdx.x, h = blockIdx.y, b = blockIdx.z;

    auto issue = [&](int kt){
        int buf = kt % 3;
        __half* dk = sK + buf*4096;
        __half* dv = sV + buf*4096;
        const __half* gk = g_k + (size_t)(b*LK + kt*64)*HID + h*64;
        const __half* gv = g_v + (size_t)(b*LK + kt*64)*HID + h*64;
#pragma unroll
        for (int it = 0; it < 4; it++){
            int idx = it*128 + t, rr = idx >> 3, c = idx & 7;
            unsigned so = rr*64 + ((c ^ (rr & 7)) << 3);
            cp16(dk + so, gk + (size_t)rr*HID + c*8);
            cp16(dv + so, gv + (size_t)rr*HID + c*8);
        }
        cp_commit();
    };

    issue(0);
    issue(1);

    // mask bias (log2 domain; huge negative saturates exp2 to 0 in f16)
    for (int i = t; i < LK; i += 128)
        skb[i] = __float2half((1.0f - kg_mask[b*LK + i]) * (-30000.0f));
    // Q tile (128 rows)
#pragma unroll
    for (int it = 0; it < 8; it++){
        int idx = it*128 + t, row = idx >> 3, c = idx & 7;
        *(uint4*)(sQ + row*64 + ((c ^ (row & 7)) << 3)) =
            *(const uint4*)(g_q + (size_t)(b*LQ + qt*128 + row)*HID + h*64 + c*8);
    }
    __syncthreads();

    // resident Q fragments: 2 rowgroups x 4 k-chunks
    unsigned qf[2][4][4];
#pragma unroll
    for (int rg = 0; rg < 2; rg++){
        int r = w*32 + rg*16 + (lane & 7) + (lane & 8);
#pragma unroll
        for (int kk = 0; kk < 4; kk++){
            int c = 2*kk + (lane >> 4);
            ldsm4(sptr(sQ + r*64 + ((c ^ (r & 7)) << 3)),
                  qf[rg][kk][0], qf[rg][kk][1], qf[rg][kk][2], qf[rg][kk][3]);
        }
    }

    unsigned O2[2][8][2] = {};                   // f16x2 accumulators
    __half2 lh[2][2] = {{__floats2half2_rn(0,0),__floats2half2_rn(0,0)},
                        {__floats2half2_rn(0,0),__floats2half2_rn(0,0)}};
    const int rB0 = (lane & 7) + ((lane & 16) >> 1);
    const int rV0 = (lane & 7) + (lane & 8);

    auto ldK = [&](__half* K, int hk, int kk, unsigned f[2][4]){
        int cB = 2*kk + ((lane >> 3) & 1);
#pragma unroll
        for (int jp = 0; jp < 2; jp++){
            int r = hk*32 + jp*16 + rB0;
            ldsm4(sptr(K + r*64 + ((cB ^ (r & 7)) << 3)), f[jp][0], f[jp][1], f[jp][2], f[jp][3]);
        }
    };
    auto ldV = [&](__half* V, int hk, int kk2, unsigned f[4][4]){
        int r = hk*32 + kk2*16 + rV0;
#pragma unroll
        for (int jp = 0; jp < 4; jp++){
            int c = 2*jp + (lane >> 4);
            ldsm4t(sptr(V + r*64 + ((c ^ (r & 7)) << 3)), f[jp][0], f[jp][1], f[jp][2], f[jp][3]);
        }
    };

    for (int kt = 0; kt < NT; kt++){
        cp_wait1();
        __syncthreads();
        if (kt + 2 < NT) issue(kt + 2);
        else cp_commit();
        __half* K = sK + (kt % 3)*4096;
        __half* V = sV + (kt % 3)*4096;

#pragma unroll
        for (int hk = 0; hk < 2; hk++){
            unsigned kfA[2][4], kfB[2][4];
            ldK(K, hk, 0, kfA);
            unsigned S2[2][4][2] = {};
#pragma unroll
            for (int kk = 0; kk < 4; kk++){
                unsigned (*cur)[4] = (kk & 1) ? kfB : kfA;
                if (kk < 3) ldK(K, hk, kk + 1, (kk & 1) ? kfA : kfB);
#pragma unroll
                for (int jp = 0; jp < 2; jp++){
                    mma_f16c(S2[0][2*jp],   qf[0][kk], cur[jp][0], cur[jp][1]);
                    mma_f16c(S2[0][2*jp+1], qf[0][kk], cur[jp][2], cur[jp][3]);
                    mma_f16c(S2[1][2*jp],   qf[1][kk], cur[jp][0], cur[jp][1]);
                    mma_f16c(S2[1][2*jp+1], qf[1][kk], cur[jp][2], cur[jp][3]);
                }
            }

            unsigned vfA[4][4], vfB[4][4];
            ldV(V, hk, 0, vfA);

            const __half2* kb2 = (const __half2*)(skb + kt*64 + hk*32);
#pragma unroll
            for (int rg = 0; rg < 2; rg++){
#pragma unroll
                for (int j = 0; j < 4; j++){
                    __half2 bias = kb2[j*4 + (lane & 3)];
                    __half2 s0 = h2exp2(__hadd2(*(__half2*)&S2[rg][j][0], bias));
                    __half2 s1 = h2exp2(__hadd2(*(__half2*)&S2[rg][j][1], bias));
                    lh[rg][0] = __hadd2(lh[rg][0], s0);
                    lh[rg][1] = __hadd2(lh[rg][1], s1);
                    S2[rg][j][0] = *(unsigned*)&s0;
                    S2[rg][j][1] = *(unsigned*)&s1;
                }
            }

#pragma unroll
            for (int kk2 = 0; kk2 < 2; kk2++){
                unsigned (*cur)[4] = (kk2 & 1) ? vfB : vfA;
                if (kk2 < 1) ldV(V, hk, 1, vfB);
#pragma unroll
                for (int jp = 0; jp < 4; jp++){
                    mma_f16c(O2[0][2*jp],   &S2[0][2*kk2][0], cur[jp][0], cur[jp][1]);
                    mma_f16c(O2[0][2*jp+1], &S2[0][2*kk2][0], cur[jp][2], cur[jp][3]);
                    mma_f16c(O2[1][2*jp],   &S2[1][2*kk2][0], cur[jp][0], cur[jp][1]);
                    mma_f16c(O2[1][2*jp+1], &S2[1][2*kk2][0], cur[jp][2], cur[jp][3]);
                }
            }
        }
    }

    // epilogue: reduce l across the quad, normalize, store
    const int g = lane >> 2, cc = (lane & 3)*2;
#pragma unroll
    for (int rg = 0; rg < 2; rg++){
        float l0 = __low2float(lh[rg][0]) + __high2float(lh[rg][0]);
        float l1 = __low2float(lh[rg][1]) + __high2float(lh[rg][1]);
        l0 += __shfl_xor_sync(0xffffffffu, l0, 1);
        l0 += __shfl_xor_sync(0xffffffffu, l0, 2);
        l1 += __shfl_xor_sync(0xffffffffu, l1, 1);
        l1 += __shfl_xor_sync(0xffffffffu, l1, 2);
        float inv0 = 1.0f / l0, inv1 = 1.0f / l1;
#pragma unroll
        for (int j = 0; j < 8; j++){
            float2 a = __half22float2(*(__half2*)&O2[rg][j][0]);
            float2 c = __half22float2(*(__half2*)&O2[rg][j][1]);
            size_t r0 = (size_t)(b*LQ + qt*128 + w*32 + rg*16 + g)*HID + h*64 + j*8 + cc;
            *(__half2*)(g_ctx + r0)         = __floats2half2_rn(a.x*inv0, a.y*inv0);
            *(__half2*)(g_ctx + r0 + 8*HID) = __floats2half2_rn(c.x*inv1, c.y*inv1);
        }
    }
}

// ---------------- output linear + gelu + residual (fused epilogue) --------------
__global__ __launch_bounds__(256) void lin_kernel(const float* __restrict__ bias,
                                                  const float* __restrict__ resid){
    extern __shared__ char sm[];
    __half* sA = (__half*)sm;            // 2 x 128x64 = 32KB
    __half* sW = (__half*)(sm + 32768);  // 2 x 128x64 = 32KB
    const int t = threadIdx.x, lane = t & 31, w = t >> 5;
    const int ct = blockIdx.x, rt = blockIdx.y;
    const int wrow = (w >> 1)*32, wcol = (w & 1)*64;

    auto issue = [&](int ki, int buf){
        __half* da = sA + buf*8192;
        __half* dw = sW + buf*8192;
#pragma unroll
        for (int it = 0; it < 4; it++){
            int idx = it*256 + t, row = idx >> 3, c = idx & 7;
            unsigned so = row*64 + ((c ^ (row & 7)) << 3);
            cp16(da + so, g_ctx + (size_t)(rt*128 + row)*HID + ki*64 + c*8);
            cp16(dw + so, g_wl  + (size_t)(ct*128 + row)*HID + ki*64 + c*8);
        }
        cp_commit();
    };

    issue(0, 0);
    issue(1, 1);

    unsigned acc2[2][8][2] = {};
    const int rB0 = (lane & 7) + ((lane & 16) >> 1);

    for (int ki = 0; ki < HID/64; ki++){
        cp_wait1();
        __syncthreads();
        __half* A  = sA + (ki & 1)*8192;
        __half* Wt = sW + (ki & 1)*8192;
#pragma unroll
        for (int kk = 0; kk < 4; kk++){
            unsigned af0[4], af1[4];
            int cA = 2*kk + (lane >> 4);
            int rA0 = wrow + (lane & 7) + (lane & 8);
            int rA1 = rA0 + 16;
            ldsm4(sptr(A + rA0*64 + ((cA ^ (rA0 & 7)) << 3)), af0[0], af0[1], af0[2], af0[3]);
            ldsm4(sptr(A + rA1*64 + ((cA ^ (rA1 & 7)) << 3)), af1[0], af1[1], af1[2], af1[3]);
            int cB = 2*kk + ((lane >> 3) & 1);
#pragma unroll
            for (int jp = 0; jp < 4; jp++){
                int r = wcol + jp*16 + rB0;
                unsigned b0, b1, b2, b3;
                ldsm4(sptr(Wt + r*64 + ((cB ^ (r & 7)) << 3)), b0, b1, b2, b3);
                mma_f16c(acc2[0][2*jp],   af0, b0, b1);
                mma_f16c(acc2[0][2*jp+1], af0, b2, b3);
                mma_f16c(acc2[1][2*jp],   af1, b0, b1);
                mma_f16c(acc2[1][2*jp+1], af1, b2, b3);
            }
        }
        __syncthreads();
        if (ki + 2 < HID/64) issue(ki + 2, ki & 1);
        else cp_commit();
    }

    // epilogue: x = gelu(lin + bias) + resid  (final kernel does LN only)
    const int g = lane >> 2, cc = (lane & 3)*2;
#pragma unroll
    for (int rg = 0; rg < 2; rg++){
#pragma unroll
        for (int j = 0; j < 8; j++){
            int col = ct*128 + wcol + j*8 + cc;
            float2 bv = *(const float2*)(bias + col);
            float2 a = __half22float2(*(__half2*)&acc2[rg][j][0]);
            float2 c = __half22float2(*(__half2*)&acc2[rg][j][1]);
            size_t row0 = (size_t)(rt*128 + wrow + rg*16 + g);
            float v0 = a.x + bv.x, v1 = a.y + bv.y;
            float v2 = c.x + bv.x, v3 = c.y + bv.y;
            float2 rs0 = *(const float2*)(resid + row0*HID + col);
            float2 rs1 = *(const float2*)(resid + (row0 + 8)*HID + col);
            float g0 = 0.5f*v0*(1.0f + erff(v0*0.70710678f)) + rs0.x;
            float g1 = 0.5f*v1*(1.0f + erff(v1*0.70710678f)) + rs0.y;
            float g2 = 0.5f*v2*(1.0f + erff(v2*0.70710678f)) + rs1.x;
            float g3 = 0.5f*v3*(1.0f + erff(v3*0.70710678f)) + rs1.y;
            *(float2*)(g_lin + row0*HID + col)       = make_float2(g0, g1);
            *(float2*)(g_lin + (row0 + 8)*HID + col) = make_float2(g2, g3);
        }
    }
}

// ---------------- layernorm only ----------------
__global__ __launch_bounds__(256) void final_kernel(const float* __restrict__ gamma,
                                                    const float* __restrict__ beta,
                                                    float* __restrict__ out){
    __shared__ float red1[8];
    __shared__ float red2[8];
    const int t = threadIdx.x;
    const size_t tok = blockIdx.x;

    float xv[4];
#pragma unroll
    for (int i = 0; i < 4; i++)
        xv[i] = g_lin[tok*HID + t + i*256];
    float s = xv[0] + xv[1] + xv[2] + xv[3];
#pragma unroll
    for (int off = 16; off; off >>= 1) s += __shfl_xor_sync(0xffffffffu, s, off);
    if ((t & 31) == 0) red1[t >> 5] = s;
    __syncthreads();
    float mu = (red1[0]+red1[1]+red1[2]+red1[3]+red1[4]+red1[5]+red1[6]+red1[7]) * (1.0f/HID);
    float v2 = 0.f;
#pragma unroll
    for (int i = 0; i < 4; i++){ float d = xv[i] - mu; v2 += d*d; }
#pragma unroll
    for (int off = 16; off; off >>= 1) v2 += __shfl_xor_sync(0xffffffffu, v2, off);
    if ((t & 31) == 0) red2[t >> 5] = v2;
    __syncthreads();
    float var = (red2[0]+red2[1]+red2[2]+red2[3]+red2[4]+red2[5]+red2[6]+red2[7]) * (1.0f/HID);
    float rstd = rsqrtf(var + 1e-5f);
#pragma unroll
    for (int i = 0; i < 4; i++){
        int c = t + i*256;
        out[tok*HID + c] = (xv[i] - mu) * rstd * gamma[c] + beta[c];
    }
}

// ---------------- launch --------------------------------------------------------
extern "C" void kernel_launch(void* const* d_in, const int* in_sizes, int n_in,
                              void* d_out, int out_size) {
    const float* input_embed = (const float*)d_in[0];
    const float* kg_embed    = (const float*)d_in[1];
    // d_in[2] input_mask: per-row constant additive shift -> softmax-invariant, unused
    const float* kg_mask     = (const float*)d_in[3];
    const float* Wq          = (const float*)d_in[4];
    const float* Wk          = (const float*)d_in[5];
    const float* Wv          = (const float*)d_in[6];
    const float* W_lin       = (const float*)d_in[7];
    const float* b_lin       = (const float*)d_in[8];
    const float* ln_gamma    = (const float*)d_in[9];
    const float* ln_beta     = (const float*)d_in[10];
    float* out = (float*)d_out;

    const int prep_smem = 32768;  // kvproj branch needs 32KB
    const int attn_smem = 69632;  // 68KB -> 3 CTAs/SM
    const int lin_smem  = 65536;
    cudaFuncSetAttribute(attn_kernel, cudaFuncAttributeMaxDynamicSharedMemorySize, attn_smem);
    cudaFuncSetAttribute(lin_kernel,  cudaFuncAttributeMaxDynamicSharedMemorySize, lin_smem);
    cudaFuncSetAttribute(attn_kernel, cudaFuncAttributePreferredSharedMemoryCarveout, 100);
    cudaFuncSetAttribute(lin_kernel,  cudaFuncAttributePreferredSharedMemoryCarveout, 100);
    cudaFuncSetAttribute(prep_kernel, cudaFuncAttributePreferredSharedMemoryCarveout, 100);

    prep_kernel  <<<2560, 256, prep_smem>>>(input_embed, kg_embed, Wq, Wk, Wv, W_lin);
    attn_kernel  <<<dim3(LQ/128, NH, BB), 128, attn_smem>>>(kg_mask);
    lin_kernel   <<<dim3(HID/128, (BB*LQ)/128), 256, lin_smem>>>(b_lin, input_embed);
    final_kernel <<<BB*LQ, 256>>>(ln_gamma, ln_beta, out);
}